// round 11
// baseline (speedup 1.0000x reference)
#include <cuda_runtime.h>
#include <cuda_bf16.h>
#include <math.h>

#define B_   2048
#define DIN_ 768
#define D_   512
#define H_   8
#define HD_  64
#define L_   3
#define P_   40
#define Q_   128
#define EPSF 1e-5f

// ---------------- scratch (device globals; no allocation allowed) ----------------
__device__ float g_feat0[B_ * D_];
__device__ float g_feat [B_ * D_];
__device__ float g_buf1 [B_ * D_];
__device__ float g_buf2 [B_ * D_];
__device__ __nv_bfloat16 g_qkvb[B_ * 3 * D_];   // bf16 qkv (q pre-scaled by 1/8)
__device__ __nv_bfloat16 g_xb  [B_ * DIN_];     // bf16 copy of x
__device__ __nv_bfloat16 g_ab1 [B_ * D_];
__device__ __nv_bfloat16 g_ab2 [B_ * D_];
__device__ __nv_bfloat16 g_ab3 [B_ * D_];
__device__ float g_z    [B_ * Q_];
__device__ __nv_bfloat16 g_wbf[5800000];         // bf16 weight pool

#define OFF_RED  0
#define OFF_IN   (OFF_RED + D_ * DIN_)
#define OFF_OUT  (OFF_IN + L_ * 3 * D_ * D_)
#define OFF_FF1  (OFF_OUT + L_ * D_ * D_)
#define OFF_FF2  (OFF_FF1 + L_ * D_ * D_)
#define OFF_M1   (OFF_FF2 + L_ * D_ * D_)
#define OFF_M2   (OFF_M1 + D_ * D_)
#define OFF_M3   (OFF_M2 + D_ * D_)

// ---------------- helpers ----------------
__device__ __forceinline__ void mma_bf16(float* c, unsigned a0, unsigned a1,
                                         unsigned a2, unsigned a3,
                                         unsigned b0, unsigned b1) {
    asm volatile(
        "mma.sync.aligned.m16n8k16.row.col.f32.bf16.bf16.f32 "
        "{%0,%1,%2,%3}, {%4,%5,%6,%7}, {%8,%9}, {%0,%1,%2,%3};"
        : "+f"(c[0]), "+f"(c[1]), "+f"(c[2]), "+f"(c[3])
        : "r"(a0), "r"(a1), "r"(a2), "r"(a3), "r"(b0), "r"(b1));
}
__device__ __forceinline__ unsigned pack_bf16(float lo, float hi) {
    unsigned r; asm("cvt.rn.bf16x2.f32 %0, %1, %2;" : "=r"(r) : "f"(hi), "f"(lo));
    return r;
}
__device__ __forceinline__ void ldsm_x4(unsigned& a, unsigned& b, unsigned& c,
                                        unsigned& d, unsigned p) {
    asm volatile("ldmatrix.sync.aligned.m8n8.x4.shared.b16 {%0,%1,%2,%3}, [%4];"
                 : "=r"(a), "=r"(b), "=r"(c), "=r"(d) : "r"(p));
}
__device__ __forceinline__ void ldsm_x4t(unsigned& a, unsigned& b, unsigned& c,
                                         unsigned& d, unsigned p) {
    asm volatile("ldmatrix.sync.aligned.m8n8.x4.trans.shared.b16 {%0,%1,%2,%3}, [%4];"
                 : "=r"(a), "=r"(b), "=r"(c), "=r"(d) : "r"(p));
}
__device__ __forceinline__ void cp16(unsigned dst, const void* src) {
    asm volatile("cp.async.cg.shared.global [%0], [%1], 16;" :: "r"(dst), "l"(src));
}

// ---------------- merged fp32 -> bf16 conversion (9 segments, 1 launch) ----------------
struct Cvt9 {
    const float* s[9];
    __nv_bfloat16* d[9];
    int cum[10];
};
__global__ __launch_bounds__(256)
void cvt_bf16_all(Cvt9 a)
{
    int gid = blockIdx.x * 256 + threadIdx.x;
    if (gid >= a.cum[9]) return;
    int seg = 0;
    #pragma unroll
    for (int i = 1; i < 9; i++) if (gid >= a.cum[i]) seg = i;
    int idx = gid - a.cum[seg];
    float4 v = ((const float4*)a.s[seg])[idx];
    uint2 r;
    r.x = pack_bf16(v.x, v.y);
    r.y = pack_bf16(v.z, v.w);
    ((uint2*)a.d[seg])[idx] = r;
}

// ============ bf16 MMA GEMM v4: 64x64 tiles, 3-stage cp.async, ldmatrix ============
// A:[M,K] bf16, W:[N,K] bf16, C:[M,N]. BM=64, BN=64, BK=32, 3 stages.
// 8 warps in 2(m) x 4(n); warp tile 32x16.
// EPI: 0 = bias, 1 = bias+relu, 2 = bias+residual(fp32)
// OUT: 0 = fp32 ; 1 = bf16 with cols<512 scaled by 0.125 (qkv) ; 2 = bf16
#define GSSZ 10240u                 // (64+64) rows * 80 B
#define GSMEM (3 * 10240)

template<int EPI, int OUT>
__global__ __launch_bounds__(256, 3)
void gemm64(const __nv_bfloat16* __restrict__ A, const __nv_bfloat16* __restrict__ W,
            const float* __restrict__ bias, const float* __restrict__ res,
            void* __restrict__ Cv, int K, int ldc)
{
    extern __shared__ unsigned char smx[];
    const unsigned smb = (unsigned)__cvta_generic_to_shared(smx);

    const int tid = threadIdx.x;
    const int w = tid >> 5, ln = tid & 31, g = ln >> 2, t = ln & 3;
    const int wm = (w >> 2) * 32, wn = (w & 3) * 16;
    const int m0 = blockIdx.y * 64, n0 = blockIdx.x * 64;

    // staging: tid<128 -> A rows, tid>=128 -> W rows. 2 threads/row, 32B each.
    const int isW = tid >> 7;                 // 0 for A, 1 for W
    const int srow = (tid & 127) >> 1;        // 0..63
    const int soff = (tid & 1) * 32;
    const char* gp = isW
        ? (const char*)(W + (size_t)(n0 + srow) * K) + soff
        : (const char*)(A + (size_t)(m0 + srow) * K) + soff;
    const unsigned sdst = (unsigned)(isW * (64 * 80) + srow * 80 + soff);

    const unsigned aAddr = (wm + (ln & 7) + ((ln >> 3) & 1) * 8) * 80 + (ln >> 4) * 16;
    const unsigned wAddr = 64 * 80 + (wn + (ln & 7) + (ln >> 4) * 8) * 80
                         + ((ln >> 3) & 1) * 16;

    float acc[2][2][4];
    #pragma unroll
    for (int mt = 0; mt < 2; mt++)
        #pragma unroll
        for (int nt = 0; nt < 2; nt++)
            #pragma unroll
            for (int i = 0; i < 4; i++) acc[mt][nt][i] = 0.f;

    const int NKT = K / 32;

    #define GISSUE(kt, slot) do {                                  \
        unsigned d0 = smb + (unsigned)(slot) * GSSZ + sdst;        \
        cp16(d0, gp + (size_t)(kt) * 64);                          \
        cp16(d0 + 16, gp + (size_t)(kt) * 64 + 16);                \
        asm volatile("cp.async.commit_group;");                    \
    } while (0)

    GISSUE(0, 0);
    GISSUE(1, 1);

    int slot2 = 2;   // (kt+2) % 3 tracked incrementally
    for (int kt = 0; kt < NKT; kt++) {
        if (kt + 1 < NKT) asm volatile("cp.async.wait_group 1;");
        else              asm volatile("cp.async.wait_group 0;");
        __syncthreads();
        if (kt + 2 < NKT) GISSUE(kt + 2, slot2);
        const int cslot = (slot2 == 2) ? 0 : (slot2 + 1) - 2 + ((slot2 + 1 < 2) ? 3 : 0);
        // cslot = kt % 3; compute directly to stay simple:
        const unsigned base = smb + (unsigned)(kt % 3) * GSSZ;
        slot2 = (slot2 == 2) ? 0 : slot2 + 1;
        (void)cslot;
        #pragma unroll
        for (int kg = 0; kg < 2; kg++) {
            unsigned a0[4], a1[4], b[4];
            ldsm_x4(a0[0], a0[1], a0[2], a0[3], base + aAddr + kg * 32);
            ldsm_x4(a1[0], a1[1], a1[2], a1[3], base + aAddr + 16 * 80 + kg * 32);
            ldsm_x4(b[0], b[1], b[2], b[3], base + wAddr + kg * 32);
            mma_bf16(acc[0][0], a0[0], a0[1], a0[2], a0[3], b[0], b[1]);
            mma_bf16(acc[0][1], a0[0], a0[1], a0[2], a0[3], b[2], b[3]);
            mma_bf16(acc[1][0], a1[0], a1[1], a1[2], a1[3], b[0], b[1]);
            mma_bf16(acc[1][1], a1[0], a1[1], a1[2], a1[3], b[2], b[3]);
        }
    }
    #undef GISSUE

    #pragma unroll
    for (int mt = 0; mt < 2; mt++) {
        const int r0 = m0 + wm + 16 * mt + g;
        #pragma unroll
        for (int nt = 0; nt < 2; nt++) {
            const int n = n0 + wn + 8 * nt + 2 * t;
            #pragma unroll
            for (int half = 0; half < 2; half++) {
                const size_t ro = (size_t)(r0 + 8 * half) * ldc;
                float2 v = { acc[mt][nt][2 * half], acc[mt][nt][2 * half + 1] };
                if (bias) { v.x += bias[n]; v.y += bias[n + 1]; }
                if (EPI == 1) { v.x = fmaxf(v.x, 0.f); v.y = fmaxf(v.y, 0.f); }
                if (EPI == 2) { v.x += res[ro + n]; v.y += res[ro + n + 1]; }
                if (OUT == 0) {
                    *(float2*)&((float*)Cv)[ro + n] = v;
                } else if (OUT == 1) {
                    const float sc = (n < 512) ? 0.125f : 1.0f;
                    *(unsigned*)&((__nv_bfloat16*)Cv)[ro + n] = pack_bf16(v.x * sc, v.y * sc);
                } else {
                    *(unsigned*)&((__nv_bfloat16*)Cv)[ro + n] = pack_bf16(v.x, v.y);
                }
            }
        }
    }
}

// ================= fused flash attention (no key-split, direct bf16 out) =============
#define KVROW 144
#define STG   (128 * KVROW)
#define ATTN_SMEM (4 * STG)

__global__ __launch_bounds__(128, 3)
void attn_fused(const __nv_bfloat16* __restrict__ qkvb, __nv_bfloat16* __restrict__ ctxb)
{
    extern __shared__ unsigned char sm[];
    const unsigned smb = (unsigned)__cvta_generic_to_shared(sm);
    const int tid = threadIdx.x;
    const int w = tid >> 5, ln = tid & 31, g = ln >> 2, t = ln & 3;
    const int h = blockIdx.y;
    const int q0 = blockIdx.x * 64;
    const char* qb = (const char*)qkvb;

    {
        const int r = tid >> 1;
        const char* src = qb + (size_t)(q0 + r) * 3072 + h * 128 + (tid & 1) * 64;
        unsigned dst = smb + r * KVROW + (tid & 1) * 64;
        cp16(dst, src); cp16(dst + 16, src + 16);
        cp16(dst + 32, src + 32); cp16(dst + 48, src + 48);
    }
    asm volatile("cp.async.commit_group;");
    asm volatile("cp.async.wait_group 0;");
    __syncthreads();
    unsigned qa[4][4];
    {
        const unsigned qaddr = smb + (16 * w + (ln & 7) + ((ln >> 3) & 1) * 8) * KVROW
                             + (ln >> 4) * 16;
        #pragma unroll
        for (int kg = 0; kg < 4; kg++)
            ldsm_x4(qa[kg][0], qa[kg][1], qa[kg][2], qa[kg][3], qaddr + kg * 32);
    }
    __syncthreads();

    const unsigned koff = ((ln & 7) + ((ln >> 4) << 3)) * KVROW + ((ln >> 3) & 1) * 16;
    const unsigned voff = ((ln & 7) + ((ln >> 3) & 1) * 8) * KVROW + (ln >> 4) * 16;

    #define ISSUE(ktg, buf) do {                                                   \
        unsigned kd = smb + (buf) * (2 * STG) + tid * KVROW;                       \
        const char* ks = qb + (size_t)((ktg) * 128 + tid) * 3072 + 1024 + h * 128; \
        _Pragma("unroll")                                                          \
        for (int c = 0; c < 8; c++) {                                              \
            cp16(kd + c * 16, ks + c * 16);                                        \
            cp16(kd + STG + c * 16, ks + 1024 + c * 16);                           \
        }                                                                          \
        asm volatile("cp.async.commit_group;");                                    \
    } while (0)

    float m0r = -1e30f, m1r = -1e30f, l0r = 0.f, l1r = 0.f;
    float o[8][4];
    #pragma unroll
    for (int nt = 0; nt < 8; nt++)
        #pragma unroll
        for (int i = 0; i < 4; i++) o[nt][i] = 0.f;

    ISSUE(0, 0);

    for (int kt = 0; kt < 16; kt++) {
        const int buf = kt & 1;
        if (kt < 15) {
            ISSUE(kt + 1, buf ^ 1);
            asm volatile("cp.async.wait_group 1;");
        } else {
            asm volatile("cp.async.wait_group 0;");
        }
        __syncthreads();
        const unsigned Kb = smb + buf * (2 * STG) + koff;
        const unsigned Vb = smb + buf * (2 * STG) + STG + voff;

        float s[16][4];
        #pragma unroll
        for (int nt = 0; nt < 16; nt++)
            #pragma unroll
            for (int i = 0; i < 4; i++) s[nt][i] = 0.f;
        #pragma unroll
        for (int j = 0; j < 8; j++) {
            #pragma unroll
            for (int kg = 0; kg < 4; kg++) {
                unsigned b0, b1, b2, b3;
                ldsm_x4(b0, b1, b2, b3, Kb + j * (16 * KVROW) + kg * 32);
                mma_bf16(s[2 * j],     qa[kg][0], qa[kg][1], qa[kg][2], qa[kg][3], b0, b1);
                mma_bf16(s[2 * j + 1], qa[kg][0], qa[kg][1], qa[kg][2], qa[kg][3], b2, b3);
            }
        }

        float mx0 = -1e30f, mx1 = -1e30f;
        #pragma unroll
        for (int nt = 0; nt < 16; nt++) {
            mx0 = fmaxf(mx0, fmaxf(s[nt][0], s[nt][1]));
            mx1 = fmaxf(mx1, fmaxf(s[nt][2], s[nt][3]));
        }
        mx0 = fmaxf(mx0, __shfl_xor_sync(0xffffffffu, mx0, 1));
        mx0 = fmaxf(mx0, __shfl_xor_sync(0xffffffffu, mx0, 2));
        mx1 = fmaxf(mx1, __shfl_xor_sync(0xffffffffu, mx1, 1));
        mx1 = fmaxf(mx1, __shfl_xor_sync(0xffffffffu, mx1, 2));
        const float mn0 = fmaxf(m0r, mx0), mn1 = fmaxf(m1r, mx1);
        const float al0 = __expf(m0r - mn0), al1 = __expf(m1r - mn1);
        m0r = mn0; m1r = mn1;
        float sum0 = 0.f, sum1 = 0.f;
        #pragma unroll
        for (int nt = 0; nt < 16; nt++) {
            s[nt][0] = __expf(s[nt][0] - mn0);
            s[nt][1] = __expf(s[nt][1] - mn0);
            s[nt][2] = __expf(s[nt][2] - mn1);
            s[nt][3] = __expf(s[nt][3] - mn1);
            sum0 += s[nt][0] + s[nt][1];
            sum1 += s[nt][2] + s[nt][3];
        }
        sum0 += __shfl_xor_sync(0xffffffffu, sum0, 1);
        sum0 += __shfl_xor_sync(0xffffffffu, sum0, 2);
        sum1 += __shfl_xor_sync(0xffffffffu, sum1, 1);
        sum1 += __shfl_xor_sync(0xffffffffu, sum1, 2);
        l0r = l0r * al0 + sum0;
        l1r = l1r * al1 + sum1;
        #pragma unroll
        for (int nt = 0; nt < 8; nt++) {
            o[nt][0] *= al0; o[nt][1] *= al0;
            o[nt][2] *= al1; o[nt][3] *= al1;
        }

        #pragma unroll
        for (int i = 0; i < 8; i++) {
            unsigned pa0 = pack_bf16(s[2 * i][0],     s[2 * i][1]);
            unsigned pa1 = pack_bf16(s[2 * i][2],     s[2 * i][3]);
            unsigned pa2 = pack_bf16(s[2 * i + 1][0], s[2 * i + 1][1]);
            unsigned pa3 = pack_bf16(s[2 * i + 1][2], s[2 * i + 1][3]);
            #pragma unroll
            for (int j = 0; j < 4; j++) {
                unsigned b0, b1, b2, b3;
                ldsm_x4t(b0, b1, b2, b3, Vb + i * (16 * KVROW) + j * 32);
                mma_bf16(o[2 * j],     pa0, pa1, pa2, pa3, b0, b1);
                mma_bf16(o[2 * j + 1], pa0, pa1, pa2, pa3, b2, b3);
            }
        }
        __syncthreads();
    }
    #undef ISSUE

    const float inv0 = 1.0f / l0r, inv1 = 1.0f / l1r;
    #pragma unroll
    for (int nt = 0; nt < 8; nt++) {
        const int n = h * 64 + 8 * nt + 2 * t;
        const size_t r0 = (size_t)(q0 + 16 * w + g) * D_;
        const size_t r1 = (size_t)(q0 + 16 * w + g + 8) * D_;
        *(unsigned*)&ctxb[r0 + n] = pack_bf16(o[nt][0] * inv0, o[nt][1] * inv0);
        *(unsigned*)&ctxb[r1 + n] = pack_bf16(o[nt][2] * inv1, o[nt][3] * inv1);
    }
}

// ---------------- per-row normalize ----------------
template<int N, bool AFFINE, bool ADD>
__global__ __launch_bounds__(128)
void rownorm(const float* __restrict__ src, const float* __restrict__ addv,
             const float* __restrict__ w, const float* __restrict__ bb,
             float* __restrict__ dst, __nv_bfloat16* __restrict__ dstb)
{
    constexpr int NPT = N / 128;
    const size_t base = (size_t)blockIdx.x * N;
    const int t = threadIdx.x;
    float v[NPT];
    float s = 0.f;
    #pragma unroll
    for (int i = 0; i < NPT; i++) { v[i] = src[base + t + i * 128]; s += v[i]; }
    __shared__ float sm[4];
    #pragma unroll
    for (int o = 16; o > 0; o >>= 1) s += __shfl_xor_sync(0xffffffffu, s, o);
    if ((t & 31) == 0) sm[t >> 5] = s;
    __syncthreads();
    s = sm[0] + sm[1] + sm[2] + sm[3];
    const float mean = s * (1.0f / N);
    float q = 0.f;
    #pragma unroll
    for (int i = 0; i < NPT; i++) { float d = v[i] - mean; q += d * d; }
    __syncthreads();
    #pragma unroll
    for (int o = 16; o > 0; o >>= 1) q += __shfl_xor_sync(0xffffffffu, q, o);
    if ((t & 31) == 0) sm[t >> 5] = q;
    __syncthreads();
    q = sm[0] + sm[1] + sm[2] + sm[3];
    const float r = rsqrtf(q * (1.0f / N) + EPSF);
    #pragma unroll
    for (int i = 0; i < NPT; i++) {
        int c = t + i * 128;
        float y = (v[i] - mean) * r;
        if (AFFINE) y = y * w[c] + bb[c];
        if (ADD)    y += addv[base + c];
        if (dst)  dst[base + c] = y;
        if (dstb) dstb[base + c] = __float2bfloat16(y);
    }
}

// ---------------- cdist to prototypes, min over P, logits ----------------
__global__ __launch_bounds__(128)
void cdist_logits(const float* __restrict__ z, const float* __restrict__ hi,
                  const float* __restrict__ neg, float* __restrict__ out)
{
    __shared__ float zr[Q_];
    __shared__ float dist[128];
    const int b = blockIdx.x, t = threadIdx.x;
    zr[t] = z[(size_t)b * Q_ + t];
    dist[t] = 3.4e38f;
    __syncthreads();
    if (t < P_) {
        const float* p = hi + (size_t)t * Q_;
        float s = 0.f;
        #pragma unroll 8
        for (int d = 0; d < Q_; d++) { float df = zr[d] - p[d]; s = fmaf(df, df, s); }
        dist[t] = sqrtf(s);
    } else if (t >= 64 && t < 64 + P_) {
        const float* p = neg + (size_t)(t - 64) * Q_;
        float s = 0.f;
        #pragma unroll 8
        for (int d = 0; d < Q_; d++) { float df = zr[d] - p[d]; s = fmaf(df, df, s); }
        dist[t] = sqrtf(s);
    }
    __syncthreads();
    if (t == 0) {
        float m = 3.4e38f;
        for (int i = 0; i < P_; i++) m = fminf(m, dist[i]);
        out[b * 2 + 1] = -m;
    }
    if (t == 32) {
        float m = 3.4e38f;
        for (int i = 0; i < P_; i++) m = fminf(m, dist[64 + i]);
        out[b * 2 + 0] = -m;
    }
}

// ---------------- host driver ----------------
extern "C" void kernel_launch(void* const* d_in, const int* in_sizes, int n_in,
                              void* d_out, int out_size)
{
    const float* x        = (const float*)d_in[0];
    const float* reduce_w = (const float*)d_in[1];
    const float* reduce_b = (const float*)d_in[2];
    const float* in_w     = (const float*)d_in[3];
    const float* in_b     = (const float*)d_in[4];
    const float* out_w    = (const float*)d_in[5];
    const float* out_b    = (const float*)d_in[6];
    const float* ff1_w    = (const float*)d_in[7];
    const float* ff1_b    = (const float*)d_in[8];
    const float* ff2_w    = (const float*)d_in[9];
    const float* ff2_b    = (const float*)d_in[10];
    const float* ln1_w    = (const float*)d_in[11];
    const float* ln1_b    = (const float*)d_in[12];
    const float* ln2_w    = (const float*)d_in[13];
    const float* ln2_b    = (const float*)d_in[14];
    const float* mlp_w1   = (const float*)d_in[15];
    const float* mlp_b1   = (const float*)d_in[16];
    const float* mlp_w2   = (const float*)d_in[17];
    const float* mlp_b2   = (const float*)d_in[18];
    const float* mlp_w3   = (const float*)d_in[19];
    const float* mlp_b3   = (const float*)d_in[20];
    const float* highlights = (const float*)d_in[21];
    const float* negatives  = (const float*)d_in[22];
    float* out = (float*)d_out;

    float *feat0, *feat, *buf1, *buf2, *z;
    __nv_bfloat16 *wbf, *qkvb, *xb, *ab1, *ab2, *ab3;
    cudaGetSymbolAddress((void**)&feat0, g_feat0);
    cudaGetSymbolAddress((void**)&feat,  g_feat);
    cudaGetSymbolAddress((void**)&buf1,  g_buf1);
    cudaGetSymbolAddress((void**)&buf2,  g_buf2);
    cudaGetSymbolAddress((void**)&qkvb,  g_qkvb);
    cudaGetSymbolAddress((void**)&xb,    g_xb);
    cudaGetSymbolAddress((void**)&ab1,   g_ab1);
    cudaGetSymbolAddress((void**)&ab2,   g_ab2);
    cudaGetSymbolAddress((void**)&ab3,   g_ab3);
    cudaGetSymbolAddress((void**)&z,     g_z);
    cudaGetSymbolAddress((void**)&wbf,   g_wbf);

    cudaFuncSetAttribute(attn_fused, cudaFuncAttributeMaxDynamicSharedMemorySize,
                         ATTN_SMEM);
    cudaFuncSetAttribute(gemm64<0, 0>, cudaFuncAttributeMaxDynamicSharedMemorySize, GSMEM);
    cudaFuncSetAttribute(gemm64<0, 1>, cudaFuncAttributeMaxDynamicSharedMemorySize, GSMEM);
    cudaFuncSetAttribute(gemm64<2, 0>, cudaFuncAttributeMaxDynamicSharedMemorySize, GSMEM);
    cudaFuncSetAttribute(gemm64<1, 2>, cudaFuncAttributeMaxDynamicSharedMemorySize, GSMEM);

    // ---- convert all weights + x to bf16 in one launch ----
    Cvt9 cv;
    const float* srcs[9] = {reduce_w, in_w, out_w, ff1_w, ff2_w, mlp_w1, mlp_w2, mlp_w3, x};
    __nv_bfloat16* dsts[9] = {wbf + OFF_RED, wbf + OFF_IN, wbf + OFF_OUT, wbf + OFF_FF1,
                              wbf + OFF_FF2, wbf + OFF_M1, wbf + OFF_M2, wbf + OFF_M3, xb};
    const int n4s[9] = {D_ * DIN_ / 4, L_ * 3 * D_ * D_ / 4, L_ * D_ * D_ / 4,
                        L_ * D_ * D_ / 4, L_ * D_ * D_ / 4, D_ * D_ / 4, D_ * D_ / 4,
                        Q_ * D_ / 4, B_ * DIN_ / 4};
    cv.cum[0] = 0;
    for (int i = 0; i < 9; i++) {
        cv.s[i] = srcs[i];
        cv.d[i] = dsts[i];
        cv.cum[i + 1] = cv.cum[i] + n4s[i];
    }
    cvt_bf16_all<<<(cv.cum[9] + 255) / 256, 256>>>(cv);

    // feat0 = inorm(x @ reduce_w^T + b)
    gemm64<0, 0><<<dim3(D_ / 64, B_ / 64), 256, GSMEM>>>(
        xb, wbf + OFF_RED, reduce_b, nullptr, buf1, DIN_, D_);
    rownorm<D_, false, false><<<B_, 128>>>(buf1, nullptr, nullptr, nullptr, feat0, ab1);

    const float* featPrev = feat0;
    for (int l = 0; l < L_; l++) {
        gemm64<0, 1><<<dim3(3 * D_ / 64, B_ / 64), 256, GSMEM>>>(
            ab1, wbf + OFF_IN + (size_t)l * 3 * D_ * D_, in_b + l * 3 * D_, nullptr,
            qkvb, D_, 3 * D_);
        attn_fused<<<dim3(B_ / 64, H_), 128, ATTN_SMEM>>>(qkvb, ab3);
        gemm64<2, 0><<<dim3(D_ / 64, B_ / 64), 256, GSMEM>>>(
            ab3, wbf + OFF_OUT + (size_t)l * D_ * D_, out_b + l * D_, featPrev, buf1, D_, D_);
        rownorm<D_, true, false><<<B_, 128>>>(buf1, nullptr, ln1_w + l * D_, ln1_b + l * D_,
                                              feat, ab1);
        gemm64<1, 2><<<dim3(D_ / 64, B_ / 64), 256, GSMEM>>>(
            ab1, wbf + OFF_FF1 + (size_t)l * D_ * D_, ff1_b + l * D_, nullptr, ab2, D_, D_);
        gemm64<2, 0><<<dim3(D_ / 64, B_ / 64), 256, GSMEM>>>(
            ab2, wbf + OFF_FF2 + (size_t)l * D_ * D_, ff2_b + l * D_, feat, buf1, D_, D_);
        rownorm<D_, true, false><<<B_, 128>>>(buf1, nullptr, ln2_w + l * D_, ln2_b + l * D_,
                                              feat, ab1);
        featPrev = feat;
    }

    rownorm<D_, false, true><<<B_, 128>>>(feat, feat0, nullptr, nullptr, nullptr, ab1);

    gemm64<1, 2><<<dim3(D_ / 64, B_ / 64), 256, GSMEM>>>(
        ab1, wbf + OFF_M1, mlp_b1, nullptr, ab2, D_, D_);
    gemm64<1, 2><<<dim3(D_ / 64, B_ / 64), 256, GSMEM>>>(
        ab2, wbf + OFF_M2, mlp_b2, nullptr, ab3, D_, D_);
    gemm64<0, 0><<<dim3(Q_ / 64, B_ / 64), 256, GSMEM>>>(
        ab3, wbf + OFF_M3, mlp_b3, nullptr, buf2, D_, Q_);
    rownorm<Q_, false, false><<<B_, 128>>>(buf2, nullptr, nullptr, nullptr, z, nullptr);

    cdist_logits<<<B_, 128>>>(z, highlights, negatives, out);
}

// round 12
// speedup vs baseline: 1.0340x; 1.0340x over previous
#include <cuda_runtime.h>
#include <cuda_bf16.h>
#include <math.h>

#define B_   2048
#define DIN_ 768
#define D_   512
#define H_   8
#define HD_  64
#define L_   3
#define P_   40
#define Q_   128
#define EPSF 1e-5f

// ---------------- scratch (device globals; no allocation allowed) ----------------
__device__ float g_feat0[B_ * D_];
__device__ float g_feat [B_ * D_];
__device__ float g_buf1 [B_ * D_];
__device__ float g_buf2 [B_ * D_];
__device__ __nv_bfloat16 g_qkvb[B_ * 3 * D_];   // bf16 qkv (q pre-scaled by 1/8)
__device__ __nv_bfloat16 g_xb  [B_ * DIN_];     // bf16 copy of x
__device__ __nv_bfloat16 g_ab1 [B_ * D_];
__device__ __nv_bfloat16 g_ab2 [B_ * D_];
__device__ __nv_bfloat16 g_ab3 [B_ * D_];
__device__ float g_z    [B_ * Q_];
__device__ __nv_bfloat16 g_wbf[5800000];         // bf16 weight pool

#define OFF_RED  0
#define OFF_IN   (OFF_RED + D_ * DIN_)
#define OFF_OUT  (OFF_IN + L_ * 3 * D_ * D_)
#define OFF_FF1  (OFF_OUT + L_ * D_ * D_)
#define OFF_FF2  (OFF_FF1 + L_ * D_ * D_)
#define OFF_M1   (OFF_FF2 + L_ * D_ * D_)
#define OFF_M2   (OFF_M1 + D_ * D_)
#define OFF_M3   (OFF_M2 + D_ * D_)

// ---------------- helpers ----------------
__device__ __forceinline__ void mma_bf16(float* c, unsigned a0, unsigned a1,
                                         unsigned a2, unsigned a3,
                                         unsigned b0, unsigned b1) {
    asm volatile(
        "mma.sync.aligned.m16n8k16.row.col.f32.bf16.bf16.f32 "
        "{%0,%1,%2,%3}, {%4,%5,%6,%7}, {%8,%9}, {%0,%1,%2,%3};"
        : "+f"(c[0]), "+f"(c[1]), "+f"(c[2]), "+f"(c[3])
        : "r"(a0), "r"(a1), "r"(a2), "r"(a3), "r"(b0), "r"(b1));
}
__device__ __forceinline__ unsigned pack_bf16(float lo, float hi) {
    unsigned r; asm("cvt.rn.bf16x2.f32 %0, %1, %2;" : "=r"(r) : "f"(hi), "f"(lo));
    return r;
}
__device__ __forceinline__ void ldsm_x4(unsigned& a, unsigned& b, unsigned& c,
                                        unsigned& d, unsigned p) {
    asm volatile("ldmatrix.sync.aligned.m8n8.x4.shared.b16 {%0,%1,%2,%3}, [%4];"
                 : "=r"(a), "=r"(b), "=r"(c), "=r"(d) : "r"(p));
}
__device__ __forceinline__ void ldsm_x4t(unsigned& a, unsigned& b, unsigned& c,
                                         unsigned& d, unsigned p) {
    asm volatile("ldmatrix.sync.aligned.m8n8.x4.trans.shared.b16 {%0,%1,%2,%3}, [%4];"
                 : "=r"(a), "=r"(b), "=r"(c), "=r"(d) : "r"(p));
}
__device__ __forceinline__ void cp16(unsigned dst, const void* src) {
    asm volatile("cp.async.cg.shared.global [%0], [%1], 16;" :: "r"(dst), "l"(src));
}

// ---------------- merged fp32 -> bf16 conversion (9 segments, 1 launch) ----------------
struct Cvt9 {
    const float* s[9];
    __nv_bfloat16* d[9];
    int cum[10];
};
__global__ __launch_bounds__(256)
void cvt_bf16_all(Cvt9 a)
{
    int gid = blockIdx.x * 256 + threadIdx.x;
    if (gid >= a.cum[9]) return;
    int seg = 0;
    #pragma unroll
    for (int i = 1; i < 9; i++) if (gid >= a.cum[i]) seg = i;
    int idx = gid - a.cum[seg];
    float4 v = ((const float4*)a.s[seg])[idx];
    uint2 r;
    r.x = pack_bf16(v.x, v.y);
    r.y = pack_bf16(v.z, v.w);
    ((uint2*)a.d[seg])[idx] = r;
}

// ============ bf16 MMA GEMM (R10 proven): 3-stage cp.async, ldmatrix ============
// A:[M,K] bf16, W:[N,K] bf16, C:[M,N]. BM=128, BK=32, 3 stages.
// EPI: 0 = bias, 1 = bias+relu, 2 = bias+residual(fp32)
// OUT: 0 = fp32 ; 1 = bf16 with cols<512 scaled by 0.125 (qkv) ; 2 = bf16
template<int BN, int EPI, int OUT>
__global__ __launch_bounds__(256)
void gemm_bf16(const __nv_bfloat16* __restrict__ A, const __nv_bfloat16* __restrict__ W,
               const float* __restrict__ bias, const float* __restrict__ res,
               void* __restrict__ Cv, int K, int ldc)
{
    constexpr int NT = BN / 16;
    constexpr int TROWS = 128 + BN;
    constexpr unsigned SSZ = TROWS * 80;
    extern __shared__ unsigned char smx[];
    const unsigned smb = (unsigned)__cvta_generic_to_shared(smx);

    const int tid = threadIdx.x;
    const int w = tid >> 5, ln = tid & 31, g = ln >> 2, t = ln & 3;
    const int wm = (w >> 1) * 32, wn = (w & 1) * (BN / 2);
    const int m0 = blockIdx.y * 128, n0 = blockIdx.x * BN;

    const int arow = tid >> 1, aoff = (tid & 1) * 32;
    const char* ap = (const char*)(A + (size_t)(m0 + arow) * K) + aoff;
    const int wrow = (BN == 128) ? (tid >> 1) : (tid >> 2);
    const int woff = (BN == 128) ? ((tid & 1) * 32) : ((tid & 3) * 16);
    const char* wp = (const char*)(W + (size_t)(n0 + wrow) * K) + woff;

    const unsigned aAddr = (wm + (ln & 7) + ((ln >> 3) & 1) * 8) * 80 + (ln >> 4) * 16;
    const unsigned wAddr = 128 * 80 + (wn + (ln & 7) + (ln >> 4) * 8) * 80
                         + ((ln >> 3) & 1) * 16;

    float acc[2][NT][4];
    #pragma unroll
    for (int mt = 0; mt < 2; mt++)
        #pragma unroll
        for (int nt = 0; nt < NT; nt++)
            #pragma unroll
            for (int i = 0; i < 4; i++) acc[mt][nt][i] = 0.f;

    const int NKT = K / 32;

    #define GISSUE(kt, slot) do {                                            \
        unsigned ad = smb + (unsigned)(slot) * SSZ + arow * 80 + aoff;       \
        cp16(ad, ap + (size_t)(kt) * 64);                                    \
        cp16(ad + 16, ap + (size_t)(kt) * 64 + 16);                          \
        unsigned wd = smb + (unsigned)(slot) * SSZ + 128 * 80 + wrow * 80 + woff; \
        cp16(wd, wp + (size_t)(kt) * 64);                                    \
        if (BN == 128) cp16(wd + 16, wp + (size_t)(kt) * 64 + 16);           \
        asm volatile("cp.async.commit_group;");                              \
    } while (0)

    GISSUE(0, 0);
    GISSUE(1, 1);

    for (int kt = 0; kt < NKT; kt++) {
        if (kt + 1 < NKT) asm volatile("cp.async.wait_group 1;");
        else              asm volatile("cp.async.wait_group 0;");
        __syncthreads();
        if (kt + 2 < NKT) GISSUE(kt + 2, (kt + 2) % 3);
        const unsigned base = smb + (unsigned)(kt % 3) * SSZ;
        #pragma unroll
        for (int kg = 0; kg < 2; kg++) {
            unsigned a[2][4];
            ldsm_x4(a[0][0], a[0][1], a[0][2], a[0][3], base + aAddr + kg * 32);
            ldsm_x4(a[1][0], a[1][1], a[1][2], a[1][3], base + aAddr + 16 * 80 + kg * 32);
            #pragma unroll
            for (int ng = 0; ng < NT / 2; ng++) {
                unsigned b0, b1, b2, b3;
                ldsm_x4(b0, b1, b2, b3, base + wAddr + ng * (16 * 80) + kg * 32);
                mma_bf16(acc[0][2 * ng],     a[0][0], a[0][1], a[0][2], a[0][3], b0, b1);
                mma_bf16(acc[0][2 * ng + 1], a[0][0], a[0][1], a[0][2], a[0][3], b2, b3);
                mma_bf16(acc[1][2 * ng],     a[1][0], a[1][1], a[1][2], a[1][3], b0, b1);
                mma_bf16(acc[1][2 * ng + 1], a[1][0], a[1][1], a[1][2], a[1][3], b2, b3);
            }
        }
    }
    #undef GISSUE

    #pragma unroll
    for (int mt = 0; mt < 2; mt++) {
        const int r0 = m0 + wm + 16 * mt + g;
        #pragma unroll
        for (int nt = 0; nt < NT; nt++) {
            const int n = n0 + wn + 8 * nt + 2 * t;
            #pragma unroll
            for (int half = 0; half < 2; half++) {
                const size_t ro = (size_t)(r0 + 8 * half) * ldc;
                float2 v = { acc[mt][nt][2 * half], acc[mt][nt][2 * half + 1] };
                if (bias) { v.x += bias[n]; v.y += bias[n + 1]; }
                if (EPI == 1) { v.x = fmaxf(v.x, 0.f); v.y = fmaxf(v.y, 0.f); }
                if (EPI == 2) { v.x += res[ro + n]; v.y += res[ro + n + 1]; }
                if (OUT == 0) {
                    *(float2*)&((float*)Cv)[ro + n] = v;
                } else if (OUT == 1) {
                    const float sc = (n < 512) ? 0.125f : 1.0f;
                    *(unsigned*)&((__nv_bfloat16*)Cv)[ro + n] = pack_bf16(v.x * sc, v.y * sc);
                } else {
                    *(unsigned*)&((__nv_bfloat16*)Cv)[ro + n] = pack_bf16(v.x, v.y);
                }
            }
        }
    }
}

// ================= fused flash attention (no key-split, direct bf16 out) =============
#define KVROW 144
#define STG   (128 * KVROW)
#define ATTN_SMEM (4 * STG)

__global__ __launch_bounds__(128, 3)
void attn_fused(const __nv_bfloat16* __restrict__ qkvb, __nv_bfloat16* __restrict__ ctxb)
{
    extern __shared__ unsigned char sm[];
    const unsigned smb = (unsigned)__cvta_generic_to_shared(sm);
    const int tid = threadIdx.x;
    const int w = tid >> 5, ln = tid & 31, g = ln >> 2, t = ln & 3;
    const int h = blockIdx.y;
    const int q0 = blockIdx.x * 64;
    const char* qb = (const char*)qkvb;

    {
        const int r = tid >> 1;
        const char* src = qb + (size_t)(q0 + r) * 3072 + h * 128 + (tid & 1) * 64;
        unsigned dst = smb + r * KVROW + (tid & 1) * 64;
        cp16(dst, src); cp16(dst + 16, src + 16);
        cp16(dst + 32, src + 32); cp16(dst + 48, src + 48);
    }
    asm volatile("cp.async.commit_group;");
    asm volatile("cp.async.wait_group 0;");
    __syncthreads();
    unsigned qa[4][4];
    {
        const unsigned qaddr = smb + (16 * w + (ln & 7) + ((ln >> 3) & 1) * 8) * KVROW
                             + (ln >> 4) * 16;
        #pragma unroll
        for (int kg = 0; kg < 4; kg++)
            ldsm_x4(qa[kg][0], qa[kg][1], qa[kg][2], qa[kg][3], qaddr + kg * 32);
    }
    __syncthreads();

    const unsigned koff = ((ln & 7) + ((ln >> 4) << 3)) * KVROW + ((ln >> 3) & 1) * 16;
    const unsigned voff = ((ln & 7) + ((ln >> 3) & 1) * 8) * KVROW + (ln >> 4) * 16;

    #define ISSUE(ktg, buf) do {                                                   \
        unsigned kd = smb + (buf) * (2 * STG) + tid * KVROW;                       \
        const char* ks = qb + (size_t)((ktg) * 128 + tid) * 3072 + 1024 + h * 128; \
        _Pragma("unroll")                                                          \
        for (int c = 0; c < 8; c++) {                                              \
            cp16(kd + c * 16, ks + c * 16);                                        \
            cp16(kd + STG + c * 16, ks + 1024 + c * 16);                           \
        }                                                                          \
        asm volatile("cp.async.commit_group;");                                    \
    } while (0)

    float m0r = -1e30f, m1r = -1e30f, l0r = 0.f, l1r = 0.f;
    float o[8][4];
    #pragma unroll
    for (int nt = 0; nt < 8; nt++)
        #pragma unroll
        for (int i = 0; i < 4; i++) o[nt][i] = 0.f;

    ISSUE(0, 0);

    for (int kt = 0; kt < 16; kt++) {
        const int buf = kt & 1;
        if (kt < 15) {
            ISSUE(kt + 1, buf ^ 1);
            asm volatile("cp.async.wait_group 1;");
        } else {
            asm volatile("cp.async.wait_group 0;");
        }
        __syncthreads();
        const unsigned Kb = smb + buf * (2 * STG) + koff;
        const unsigned Vb = smb + buf * (2 * STG) + STG + voff;

        float s[16][4];
        #pragma unroll
        for (int nt = 0; nt < 16; nt++)
            #pragma unroll
            for (int i = 0; i < 4; i++) s[nt][i] = 0.f;
        #pragma unroll
        for (int j = 0; j < 8; j++) {
            #pragma unroll
            for (int kg = 0; kg < 4; kg++) {
                unsigned b0, b1, b2, b3;
                ldsm_x4(b0, b1, b2, b3, Kb + j * (16 * KVROW) + kg * 32);
                mma_bf16(s[2 * j],     qa[kg][0], qa[kg][1], qa[kg][2], qa[kg][3], b0, b1);
                mma_bf16(s[2 * j + 1], qa[kg][0], qa[kg][1], qa[kg][2], qa[kg][3], b2, b3);
            }
        }

        float mx0 = -1e30f, mx1 = -1e30f;
        #pragma unroll
        for (int nt = 0; nt < 16; nt++) {
            mx0 = fmaxf(mx0, fmaxf(s[nt][0], s[nt][1]));
            mx1 = fmaxf(mx1, fmaxf(s[nt][2], s[nt][3]));
        }
        mx0 = fmaxf(mx0, __shfl_xor_sync(0xffffffffu, mx0, 1));
        mx0 = fmaxf(mx0, __shfl_xor_sync(0xffffffffu, mx0, 2));
        mx1 = fmaxf(mx1, __shfl_xor_sync(0xffffffffu, mx1, 1));
        mx1 = fmaxf(mx1, __shfl_xor_sync(0xffffffffu, mx1, 2));
        const float mn0 = fmaxf(m0r, mx0), mn1 = fmaxf(m1r, mx1);
        const float al0 = __expf(m0r - mn0), al1 = __expf(m1r - mn1);
        m0r = mn0; m1r = mn1;
        float sum0 = 0.f, sum1 = 0.f;
        #pragma unroll
        for (int nt = 0; nt < 16; nt++) {
            s[nt][0] = __expf(s[nt][0] - mn0);
            s[nt][1] = __expf(s[nt][1] - mn0);
            s[nt][2] = __expf(s[nt][2] - mn1);
            s[nt][3] = __expf(s[nt][3] - mn1);
            sum0 += s[nt][0] + s[nt][1];
            sum1 += s[nt][2] + s[nt][3];
        }
        sum0 += __shfl_xor_sync(0xffffffffu, sum0, 1);
        sum0 += __shfl_xor_sync(0xffffffffu, sum0, 2);
        sum1 += __shfl_xor_sync(0xffffffffu, sum1, 1);
        sum1 += __shfl_xor_sync(0xffffffffu, sum1, 2);
        l0r = l0r * al0 + sum0;
        l1r = l1r * al1 + sum1;
        #pragma unroll
        for (int nt = 0; nt < 8; nt++) {
            o[nt][0] *= al0; o[nt][1] *= al0;
            o[nt][2] *= al1; o[nt][3] *= al1;
        }

        #pragma unroll
        for (int i = 0; i < 8; i++) {
            unsigned pa0 = pack_bf16(s[2 * i][0],     s[2 * i][1]);
            unsigned pa1 = pack_bf16(s[2 * i][2],     s[2 * i][3]);
            unsigned pa2 = pack_bf16(s[2 * i + 1][0], s[2 * i + 1][1]);
            unsigned pa3 = pack_bf16(s[2 * i + 1][2], s[2 * i + 1][3]);
            #pragma unroll
            for (int j = 0; j < 4; j++) {
                unsigned b0, b1, b2, b3;
                ldsm_x4t(b0, b1, b2, b3, Vb + i * (16 * KVROW) + j * 32);
                mma_bf16(o[2 * j],     pa0, pa1, pa2, pa3, b0, b1);
                mma_bf16(o[2 * j + 1], pa0, pa1, pa2, pa3, b2, b3);
            }
        }
        __syncthreads();
    }
    #undef ISSUE

    const float inv0 = 1.0f / l0r, inv1 = 1.0f / l1r;
    #pragma unroll
    for (int nt = 0; nt < 8; nt++) {
        const int n = h * 64 + 8 * nt + 2 * t;
        const size_t r0 = (size_t)(q0 + 16 * w + g) * D_;
        const size_t r1 = (size_t)(q0 + 16 * w + g + 8) * D_;
        *(unsigned*)&ctxb[r0 + n] = pack_bf16(o[nt][0] * inv0, o[nt][1] * inv0);
        *(unsigned*)&ctxb[r1 + n] = pack_bf16(o[nt][2] * inv1, o[nt][3] * inv1);
    }
}

// ---------------- warp-per-row normalize (no barriers, no smem) ----------------
// 128 threads = 4 warps = 4 rows per block.
template<int N, bool AFFINE, bool ADD>
__global__ __launch_bounds__(128)
void rownorm_w(const float* __restrict__ src, const float* __restrict__ addv,
               const float* __restrict__ w, const float* __restrict__ bb,
               float* __restrict__ dst, __nv_bfloat16* __restrict__ dstb)
{
    constexpr int NV = N / 128;       // float4s per lane (4 for N=512, 1 for N=128)
    const int ln = threadIdx.x & 31;
    const int row = blockIdx.x * 4 + (threadIdx.x >> 5);
    const size_t base = (size_t)row * N;

    float4 v[NV];
    float s = 0.f;
    #pragma unroll
    for (int i = 0; i < NV; i++) {
        v[i] = *(const float4*)&src[base + i * 128 + ln * 4];
        s += v[i].x + v[i].y + v[i].z + v[i].w;
    }
    #pragma unroll
    for (int o = 16; o > 0; o >>= 1) s += __shfl_xor_sync(0xffffffffu, s, o);
    const float mean = s * (1.0f / N);
    float q = 0.f;
    #pragma unroll
    for (int i = 0; i < NV; i++) {
        float d0 = v[i].x - mean, d1 = v[i].y - mean;
        float d2 = v[i].z - mean, d3 = v[i].w - mean;
        q += d0 * d0 + d1 * d1 + d2 * d2 + d3 * d3;
    }
    #pragma unroll
    for (int o = 16; o > 0; o >>= 1) q += __shfl_xor_sync(0xffffffffu, q, o);
    const float r = rsqrtf(q * (1.0f / N) + EPSF);

    #pragma unroll
    for (int i = 0; i < NV; i++) {
        const int c = i * 128 + ln * 4;
        float y0 = (v[i].x - mean) * r, y1 = (v[i].y - mean) * r;
        float y2 = (v[i].z - mean) * r, y3 = (v[i].w - mean) * r;
        if (AFFINE) {
            float4 ww = *(const float4*)&w[c];
            float4 bv = *(const float4*)&bb[c];
            y0 = y0 * ww.x + bv.x; y1 = y1 * ww.y + bv.y;
            y2 = y2 * ww.z + bv.z; y3 = y3 * ww.w + bv.w;
        }
        if (ADD) {
            float4 av = *(const float4*)&addv[base + c];
            y0 += av.x; y1 += av.y; y2 += av.z; y3 += av.w;
        }
        if (dst) {
            float4 ov = {y0, y1, y2, y3};
            *(float4*)&dst[base + c] = ov;
        }
        if (dstb) {
            uint2 ob;
            ob.x = pack_bf16(y0, y1);
            ob.y = pack_bf16(y2, y3);
            *(uint2*)&dstb[base + c] = ob;
        }
    }
}

// ---------------- cdist to prototypes, min over P, logits ----------------
__global__ __launch_bounds__(128)
void cdist_logits(const float* __restrict__ z, const float* __restrict__ hi,
                  const float* __restrict__ neg, float* __restrict__ out)
{
    __shared__ float zr[Q_];
    const int b = blockIdx.x, t = threadIdx.x;
    const int ln = t & 31, wv = t >> 5;
    zr[t] = z[(size_t)b * Q_ + t];
    __syncthreads();
    // warps 0-1: positives (proto = wv*32+ln over 64 slots, valid < P_)
    // warps 2-3: negatives
    const int slot = (wv & 1) * 32 + ln;
    const float* pb = (wv < 2) ? hi : neg;
    float d = 3.4e38f;
    if (slot < P_) {
        const float* p = pb + (size_t)slot * Q_;
        float s = 0.f;
        #pragma unroll 8
        for (int k = 0; k < Q_; k++) { float df = zr[k] - p[k]; s = fmaf(df, df, s); }
        d = sqrtf(s);
    }
    #pragma unroll
    for (int o = 16; o > 0; o >>= 1) d = fminf(d, __shfl_xor_sync(0xffffffffu, d, o));
    __shared__ float mins[4];
    if (ln == 0) mins[wv] = d;
    __syncthreads();
    if (t == 0) out[b * 2 + 1] = -fminf(mins[0], mins[1]);   // -positive_dist
    if (t == 64) out[b * 2 + 0] = -fminf(mins[2], mins[3]);  // -negative_dist
}

// ---------------- host driver ----------------
extern "C" void kernel_launch(void* const* d_in, const int* in_sizes, int n_in,
                              void* d_out, int out_size)
{
    const float* x        = (const float*)d_in[0];
    const float* reduce_w = (const float*)d_in[1];
    const float* reduce_b = (const float*)d_in[2];
    const float* in_w     = (const float*)d_in[3];
    const float* in_b     = (const float*)d_in[4];
    const float* out_w    = (const float*)d_in[5];
    const float* out_b    = (const float*)d_in[6];
    const float* ff1_w    = (const float*)d_in[7];
    const float* ff1_b    = (const float*)d_in[8];
    const float* ff2_w    = (const float*)d_in[9];
    const float* ff2_b    = (const float*)d_in[10];
    const float* ln1_w    = (const float*)d_in[11];
    const float* ln1_b    = (const float*)d_in[12];
    const float* ln2_w    = (const float*)d_in[13];
    const float* ln2_b    = (const float*)d_in[14];
    const float* mlp_w1   = (const float*)d_in[15];
    const float* mlp_b1   = (const float*)d_in[16];
    const float* mlp_w2   = (const float*)d_in[17];
    const float* mlp_b2   = (const float*)d_in[18];
    const float* mlp_w3   = (const float*)d_in[19];
    const float* mlp_b3   = (const float*)d_in[20];
    const float* highlights = (const float*)d_in[21];
    const float* negatives  = (const float*)d_in[22];
    float* out = (float*)d_out;

    float *feat0, *feat, *buf1, *buf2, *z;
    __nv_bfloat16 *wbf, *qkvb, *xb, *ab1, *ab2, *ab3;
    cudaGetSymbolAddress((void**)&feat0, g_feat0);
    cudaGetSymbolAddress((void**)&feat,  g_feat);
    cudaGetSymbolAddress((void**)&buf1,  g_buf1);
    cudaGetSymbolAddress((void**)&buf2,  g_buf2);
    cudaGetSymbolAddress((void**)&qkvb,  g_qkvb);
    cudaGetSymbolAddress((void**)&xb,    g_xb);
    cudaGetSymbolAddress((void**)&ab1,   g_ab1);
    cudaGetSymbolAddress((void**)&ab2,   g_ab2);
    cudaGetSymbolAddress((void**)&ab3,   g_ab3);
    cudaGetSymbolAddress((void**)&z,     g_z);
    cudaGetSymbolAddress((void**)&wbf,   g_wbf);

    cudaFuncSetAttribute(attn_fused, cudaFuncAttributeMaxDynamicSharedMemorySize,
                         ATTN_SMEM);
    const int SM64  = 3 * (128 + 64) * 80;    // 46080
    const int SM128 = 3 * (128 + 128) * 80;   // 61440
    cudaFuncSetAttribute(gemm_bf16<64, 0, 0>,  cudaFuncAttributeMaxDynamicSharedMemorySize, SM64);
    cudaFuncSetAttribute(gemm_bf16<128, 0, 1>, cudaFuncAttributeMaxDynamicSharedMemorySize, SM128);
    cudaFuncSetAttribute(gemm_bf16<64, 2, 0>,  cudaFuncAttributeMaxDynamicSharedMemorySize, SM64);
    cudaFuncSetAttribute(gemm_bf16<64, 1, 2>,  cudaFuncAttributeMaxDynamicSharedMemorySize, SM64);

    // ---- convert all weights + x to bf16 in one launch ----
    Cvt9 cv;
    const float* srcs[9] = {reduce_w, in_w, out_w, ff1_w, ff2_w, mlp_w1, mlp_w2, mlp_w3, x};
    __nv_bfloat16* dsts[9] = {wbf + OFF_RED, wbf + OFF_IN, wbf + OFF_OUT, wbf + OFF_FF1,
                              wbf + OFF_FF2, wbf + OFF_M1, wbf + OFF_M2, wbf + OFF_M3, xb};
    const int n4s[9] = {D_ * DIN_ / 4, L_ * 3 * D_ * D_ / 4, L_ * D_ * D_ / 4,
                        L_ * D_ * D_ / 4, L_ * D_ * D_ / 4, D_ * D_ / 4, D_ * D_ / 4,
                        Q_ * D_ / 4, B_ * DIN_ / 4};
    cv.cum[0] = 0;
    for (int i = 0; i < 9; i++) {
        cv.s[i] = srcs[i];
        cv.d[i] = dsts[i];
        cv.cum[i + 1] = cv.cum[i] + n4s[i];
    }
    cvt_bf16_all<<<(cv.cum[9] + 255) / 256, 256>>>(cv);

    // feat0 = inorm(x @ reduce_w^T + b)
    gemm_bf16<64, 0, 0><<<dim3(D_ / 64, B_ / 128), 256, SM64>>>(
        xb, wbf + OFF_RED, reduce_b, nullptr, buf1, DIN_, D_);
    rownorm_w<D_, false, false><<<B_ / 4, 128>>>(buf1, nullptr, nullptr, nullptr, feat0, ab1);

    const float* featPrev = feat0;
    for (int l = 0; l < L_; l++) {
        gemm_bf16<128, 0, 1><<<dim3(3 * D_ / 128, B_ / 128), 256, SM128>>>(
            ab1, wbf + OFF_IN + (size_t)l * 3 * D_ * D_, in_b + l * 3 * D_, nullptr,
            qkvb, D_, 3 * D_);
        attn_fused<<<dim3(B_ / 64, H_), 128, ATTN_SMEM>>>(qkvb, ab3);
        gemm_bf16<64, 2, 0><<<dim3(D_ / 64, B_ / 128), 256, SM64>>>(
            ab3, wbf + OFF_OUT + (size_t)l * D_ * D_, out_b + l * D_, featPrev, buf1, D_, D_);
        rownorm_w<D_, true, false><<<B_ / 4, 128>>>(buf1, nullptr, ln1_w + l * D_,
                                                    ln1_b + l * D_, feat, ab1);
        gemm_bf16<64, 1, 2><<<dim3(D_ / 64, B_ / 128), 256, SM64>>>(
            ab1, wbf + OFF_FF1 + (size_t)l * D_ * D_, ff1_b + l * D_, nullptr, ab2, D_, D_);
        gemm_bf16<64, 2, 0><<<dim3(D_ / 64, B_ / 128), 256, SM64>>>(
            ab2, wbf + OFF_FF2 + (size_t)l * D_ * D_, ff2_b + l * D_, feat, buf1, D_, D_);
        rownorm_w<D_, true, false><<<B_ / 4, 128>>>(buf1, nullptr, ln2_w + l * D_,
                                                    ln2_b + l * D_, feat, ab1);
        featPrev = feat;
    }

    rownorm_w<D_, false, true><<<B_ / 4, 128>>>(feat, feat0, nullptr, nullptr, nullptr, ab1);

    gemm_bf16<64, 1, 2><<<dim3(D_ / 64, B_ / 128), 256, SM64>>>(
        ab1, wbf + OFF_M1, mlp_b1, nullptr, ab2, D_, D_);
    gemm_bf16<64, 1, 2><<<dim3(D_ / 64, B_ / 128), 256, SM64>>>(
        ab2, wbf + OFF_M2, mlp_b2, nullptr, ab3, D_, D_);
    gemm_bf16<64, 0, 0><<<dim3(Q_ / 64, B_ / 128), 256, SM64>>>(
        ab3, wbf + OFF_M3, mlp_b3, nullptr, buf2, D_, Q_);
    rownorm_w<Q_, false, false><<<B_ / 4, 128>>>(buf2, nullptr, nullptr, nullptr, z, nullptr);

    cdist_logits<<<B_, 128>>>(z, highlights, negatives, out);
}

// round 13
// speedup vs baseline: 1.0395x; 1.0053x over previous
#include <cuda_runtime.h>
#include <cuda_bf16.h>
#include <math.h>

#define B_   2048
#define DIN_ 768
#define D_   512
#define H_   8
#define HD_  64
#define L_   3
#define P_   40
#define Q_   128
#define EPSF 1e-5f

// ---------------- scratch (device globals; no allocation allowed) ----------------
__device__ float g_feat0[B_ * D_];
__device__ float g_feat [B_ * D_];
__device__ float g_buf1 [B_ * D_];
__device__ float g_buf2 [B_ * D_];
__device__ __nv_bfloat16 g_qkvb[B_ * 3 * D_];   // bf16 qkv (q pre-scaled by 1/8)
__device__ __nv_bfloat16 g_xb  [B_ * DIN_];     // bf16 copy of x
__device__ __nv_bfloat16 g_ab1 [B_ * D_];
__device__ __nv_bfloat16 g_ab2 [B_ * D_];
__device__ __nv_bfloat16 g_ab3 [B_ * D_];
__device__ float g_z    [B_ * Q_];
__device__ __nv_bfloat16 g_wbf[5800000];         // bf16 weight pool

#define OFF_RED  0
#define OFF_IN   (OFF_RED + D_ * DIN_)
#define OFF_OUT  (OFF_IN + L_ * 3 * D_ * D_)
#define OFF_FF1  (OFF_OUT + L_ * D_ * D_)
#define OFF_FF2  (OFF_FF1 + L_ * D_ * D_)
#define OFF_M1   (OFF_FF2 + L_ * D_ * D_)
#define OFF_M2   (OFF_M1 + D_ * D_)
#define OFF_M3   (OFF_M2 + D_ * D_)

// ---------------- helpers ----------------
__device__ __forceinline__ void mma_bf16(float* c, unsigned a0, unsigned a1,
                                         unsigned a2, unsigned a3,
                                         unsigned b0, unsigned b1) {
    asm volatile(
        "mma.sync.aligned.m16n8k16.row.col.f32.bf16.bf16.f32 "
        "{%0,%1,%2,%3}, {%4,%5,%6,%7}, {%8,%9}, {%0,%1,%2,%3};"
        : "+f"(c[0]), "+f"(c[1]), "+f"(c[2]), "+f"(c[3])
        : "r"(a0), "r"(a1), "r"(a2), "r"(a3), "r"(b0), "r"(b1));
}
__device__ __forceinline__ unsigned pack_bf16(float lo, float hi) {
    unsigned r; asm("cvt.rn.bf16x2.f32 %0, %1, %2;" : "=r"(r) : "f"(hi), "f"(lo));
    return r;
}
__device__ __forceinline__ void ldsm_x4(unsigned& a, unsigned& b, unsigned& c,
                                        unsigned& d, unsigned p) {
    asm volatile("ldmatrix.sync.aligned.m8n8.x4.shared.b16 {%0,%1,%2,%3}, [%4];"
                 : "=r"(a), "=r"(b), "=r"(c), "=r"(d) : "r"(p));
}
__device__ __forceinline__ void ldsm_x4t(unsigned& a, unsigned& b, unsigned& c,
                                         unsigned& d, unsigned p) {
    asm volatile("ldmatrix.sync.aligned.m8n8.x4.trans.shared.b16 {%0,%1,%2,%3}, [%4];"
                 : "=r"(a), "=r"(b), "=r"(c), "=r"(d) : "r"(p));
}
__device__ __forceinline__ void cp16(unsigned dst, const void* src) {
    asm volatile("cp.async.cg.shared.global [%0], [%1], 16;" :: "r"(dst), "l"(src));
}

// ---------------- merged fp32 -> bf16 conversion (9 segments, 1 launch) ----------------
struct Cvt9 {
    const float* s[9];
    __nv_bfloat16* d[9];
    int cum[10];
};
__global__ __launch_bounds__(256)
void cvt_bf16_all(Cvt9 a)
{
    int gid = blockIdx.x * 256 + threadIdx.x;
    if (gid >= a.cum[9]) return;
    int seg = 0;
    #pragma unroll
    for (int i = 1; i < 9; i++) if (gid >= a.cum[i]) seg = i;
    int idx = gid - a.cum[seg];
    float4 v = ((const float4*)a.s[seg])[idx];
    uint2 r;
    r.x = pack_bf16(v.x, v.y);
    r.y = pack_bf16(v.z, v.w);
    ((uint2*)a.d[seg])[idx] = r;
}

// ============ bf16 MMA GEMM: 3-stage cp.async, 1 sync/tile, ldmatrix ============
// A:[M,K] bf16, W:[N,K] bf16, C:[M,N]. BM=128, BK=32, 3 stages.
// EPI: 0 = bias, 1 = bias+relu, 2 = bias+residual(fp32)
// OUT: 0 = fp32 ; 1 = bf16 with cols<512 scaled by 0.125 (qkv) ; 2 = bf16
template<int BN, int EPI, int OUT>
__global__ __launch_bounds__(256, 2)
void gemm_bf16(const __nv_bfloat16* __restrict__ A, const __nv_bfloat16* __restrict__ W,
               const float* __restrict__ bias, const float* __restrict__ res,
               void* __restrict__ Cv, int K, int ldc)
{
    constexpr int NT = BN / 16;
    constexpr int TROWS = 128 + BN;
    constexpr unsigned SSZ = TROWS * 80;
    extern __shared__ unsigned char smx[];
    const unsigned smb = (unsigned)__cvta_generic_to_shared(smx);

    const int tid = threadIdx.x;
    const int w = tid >> 5, ln = tid & 31, g = ln >> 2, t = ln & 3;
    const int wm = (w >> 1) * 32, wn = (w & 1) * (BN / 2);
    const int m0 = blockIdx.y * 128, n0 = blockIdx.x * BN;

    const int arow = tid >> 1, aoff = (tid & 1) * 32;
    const char* ap = (const char*)(A + (size_t)(m0 + arow) * K) + aoff;
    const int wrow = (BN == 128) ? (tid >> 1) : (tid >> 2);
    const int woff = (BN == 128) ? ((tid & 1) * 32) : ((tid & 3) * 16);
    const char* wp = (const char*)(W + (size_t)(n0 + wrow) * K) + woff;

    const unsigned aAddr = (wm + (ln & 7) + ((ln >> 3) & 1) * 8) * 80 + (ln >> 4) * 16;
    const unsigned wAddr = 128 * 80 + (wn + (ln & 7) + (ln >> 4) * 8) * 80
                         + ((ln >> 3) & 1) * 16;

    float acc[2][NT][4];
    #pragma unroll
    for (int mt = 0; mt < 2; mt++)
        #pragma unroll
        for (int nt = 0; nt < NT; nt++)
            #pragma unroll
            for (int i = 0; i < 4; i++) acc[mt][nt][i] = 0.f;

    const int NKT = K / 32;

    #define GISSUE(kt, slot) do {                                            \
        unsigned ad = smb + (unsigned)(slot) * SSZ + arow * 80 + aoff;       \
        cp16(ad, ap + (size_t)(kt) * 64);                                    \
        cp16(ad + 16, ap + (size_t)(kt) * 64 + 16);                          \
        unsigned wd = smb + (unsigned)(slot) * SSZ + 128 * 80 + wrow * 80 + woff; \
        cp16(wd, wp + (size_t)(kt) * 64);                                    \
        if (BN == 128) cp16(wd + 16, wp + (size_t)(kt) * 64 + 16);           \
        asm volatile("cp.async.commit_group;");                              \
    } while (0)

    GISSUE(0, 0);
    GISSUE(1, 1);

    for (int kt = 0; kt < NKT; kt++) {
        if (kt + 1 < NKT) asm volatile("cp.async.wait_group 1;");
        else              asm volatile("cp.async.wait_group 0;");
        __syncthreads();
        if (kt + 2 < NKT) GISSUE(kt + 2, (kt + 2) % 3);
        const unsigned base = smb + (unsigned)(kt % 3) * SSZ;
        #pragma unroll
        for (int kg = 0; kg < 2; kg++) {
            unsigned a[2][4];
            ldsm_x4(a[0][0], a[0][1], a[0][2], a[0][3], base + aAddr + kg * 32);
            ldsm_x4(a[1][0], a[1][1], a[1][2], a[1][3], base + aAddr + 16 * 80 + kg * 32);
            #pragma unroll
            for (int ng = 0; ng < NT / 2; ng++) {
                unsigned b0, b1, b2, b3;
                ldsm_x4(b0, b1, b2, b3, base + wAddr + ng * (16 * 80) + kg * 32);
                mma_bf16(acc[0][2 * ng],     a[0][0], a[0][1], a[0][2], a[0][3], b0, b1);
                mma_bf16(acc[0][2 * ng + 1], a[0][0], a[0][1], a[0][2], a[0][3], b2, b3);
                mma_bf16(acc[1][2 * ng],     a[1][0], a[1][1], a[1][2], a[1][3], b0, b1);
                mma_bf16(acc[1][2 * ng + 1], a[1][0], a[1][1], a[1][2], a[1][3], b2, b3);
            }
        }
    }
    #undef GISSUE

    #pragma unroll
    for (int mt = 0; mt < 2; mt++) {
        const int r0 = m0 + wm + 16 * mt + g;
        #pragma unroll
        for (int nt = 0; nt < NT; nt++) {
            const int n = n0 + wn + 8 * nt + 2 * t;
            #pragma unroll
            for (int half = 0; half < 2; half++) {
                const size_t ro = (size_t)(r0 + 8 * half) * ldc;
                float2 v = { acc[mt][nt][2 * half], acc[mt][nt][2 * half + 1] };
                if (bias) { v.x += bias[n]; v.y += bias[n + 1]; }
                if (EPI == 1) { v.x = fmaxf(v.x, 0.f); v.y = fmaxf(v.y, 0.f); }
                if (EPI == 2) { v.x += res[ro + n]; v.y += res[ro + n + 1]; }
                if (OUT == 0) {
                    *(float2*)&((float*)Cv)[ro + n] = v;
                } else if (OUT == 1) {
                    const float sc = (n < 512) ? 0.125f : 1.0f;
                    *(unsigned*)&((__nv_bfloat16*)Cv)[ro + n] = pack_bf16(v.x * sc, v.y * sc);
                } else {
                    *(unsigned*)&((__nv_bfloat16*)Cv)[ro + n] = pack_bf16(v.x, v.y);
                }
            }
        }
    }
}

// ================= fused flash attention: 1 sync per K-tile =============
#define KVROW 144
#define STG   (128 * KVROW)
#define ATTN_SMEM (4 * STG)

__global__ __launch_bounds__(128, 3)
void attn_fused(const __nv_bfloat16* __restrict__ qkvb, __nv_bfloat16* __restrict__ ctxb)
{
    extern __shared__ unsigned char sm[];
    const unsigned smb = (unsigned)__cvta_generic_to_shared(sm);
    const int tid = threadIdx.x;
    const int w = tid >> 5, ln = tid & 31, g = ln >> 2, t = ln & 3;
    const int h = blockIdx.y;
    const int q0 = blockIdx.x * 64;
    const char* qb = (const char*)qkvb;

    // ---- stage Q (scaled at qkv GEMM) into stage-0 K region, extract fragments ----
    {
        const int r = tid >> 1;
        const char* src = qb + (size_t)(q0 + r) * 3072 + h * 128 + (tid & 1) * 64;
        unsigned dst = smb + r * KVROW + (tid & 1) * 64;
        cp16(dst, src); cp16(dst + 16, src + 16);
        cp16(dst + 32, src + 32); cp16(dst + 48, src + 48);
    }
    asm volatile("cp.async.commit_group;");
    asm volatile("cp.async.wait_group 0;");
    __syncthreads();
    unsigned qa[4][4];
    {
        const unsigned qaddr = smb + (16 * w + (ln & 7) + ((ln >> 3) & 1) * 8) * KVROW
                             + (ln >> 4) * 16;
        #pragma unroll
        for (int kg = 0; kg < 4; kg++)
            ldsm_x4(qa[kg][0], qa[kg][1], qa[kg][2], qa[kg][3], qaddr + kg * 32);
    }
    __syncthreads();

    const unsigned koff = ((ln & 7) + ((ln >> 4) << 3)) * KVROW + ((ln >> 3) & 1) * 16;
    const unsigned voff = ((ln & 7) + ((ln >> 3) & 1) * 8) * KVROW + (ln >> 4) * 16;

    #define ISSUE(ktg, buf) do {                                                   \
        unsigned kd = smb + (buf) * (2 * STG) + tid * KVROW;                       \
        const char* ks = qb + (size_t)((ktg) * 128 + tid) * 3072 + 1024 + h * 128; \
        _Pragma("unroll")                                                          \
        for (int c = 0; c < 8; c++) {                                              \
            cp16(kd + c * 16, ks + c * 16);                                        \
            cp16(kd + STG + c * 16, ks + 1024 + c * 16);                           \
        }                                                                          \
        asm volatile("cp.async.commit_group;");                                    \
    } while (0)

    float m0r = -1e30f, m1r = -1e30f, l0r = 0.f, l1r = 0.f;
    float o[8][4];
    #pragma unroll
    for (int nt = 0; nt < 8; nt++)
        #pragma unroll
        for (int i = 0; i < 4; i++) o[nt][i] = 0.f;

    ISSUE(0, 0);

    for (int kt = 0; kt < 16; kt++) {
        const int buf = kt & 1;
        asm volatile("cp.async.wait_group 0;");
        __syncthreads();                       // data visible + prev compute on buf^1 done
        if (kt < 15) ISSUE(kt + 1, buf ^ 1);   // overlap next load with this compute
        const unsigned Kb = smb + buf * (2 * STG) + koff;
        const unsigned Vb = smb + buf * (2 * STG) + STG + voff;

        float s[16][4];
        #pragma unroll
        for (int nt = 0; nt < 16; nt++)
            #pragma unroll
            for (int i = 0; i < 4; i++) s[nt][i] = 0.f;
        #pragma unroll
        for (int j = 0; j < 8; j++) {
            #pragma unroll
            for (int kg = 0; kg < 4; kg++) {
                unsigned b0, b1, b2, b3;
                ldsm_x4(b0, b1, b2, b3, Kb + j * (16 * KVROW) + kg * 32);
                mma_bf16(s[2 * j],     qa[kg][0], qa[kg][1], qa[kg][2], qa[kg][3], b0, b1);
                mma_bf16(s[2 * j + 1], qa[kg][0], qa[kg][1], qa[kg][2], qa[kg][3], b2, b3);
            }
        }

        float mx0 = -1e30f, mx1 = -1e30f;
        #pragma unroll
        for (int nt = 0; nt < 16; nt++) {
            mx0 = fmaxf(mx0, fmaxf(s[nt][0], s[nt][1]));
            mx1 = fmaxf(mx1, fmaxf(s[nt][2], s[nt][3]));
        }
        mx0 = fmaxf(mx0, __shfl_xor_sync(0xffffffffu, mx0, 1));
        mx0 = fmaxf(mx0, __shfl_xor_sync(0xffffffffu, mx0, 2));
        mx1 = fmaxf(mx1, __shfl_xor_sync(0xffffffffu, mx1, 1));
        mx1 = fmaxf(mx1, __shfl_xor_sync(0xffffffffu, mx1, 2));
        const float mn0 = fmaxf(m0r, mx0), mn1 = fmaxf(m1r, mx1);
        const float al0 = __expf(m0r - mn0), al1 = __expf(m1r - mn1);
        m0r = mn0; m1r = mn1;
        float sum0 = 0.f, sum1 = 0.f;
        #pragma unroll
        for (int nt = 0; nt < 16; nt++) {
            s[nt][0] = __expf(s[nt][0] - mn0);
            s[nt][1] = __expf(s[nt][1] - mn0);
            s[nt][2] = __expf(s[nt][2] - mn1);
            s[nt][3] = __expf(s[nt][3] - mn1);
            sum0 += s[nt][0] + s[nt][1];
            sum1 += s[nt][2] + s[nt][3];
        }
        sum0 += __shfl_xor_sync(0xffffffffu, sum0, 1);
        sum0 += __shfl_xor_sync(0xffffffffu, sum0, 2);
        sum1 += __shfl_xor_sync(0xffffffffu, sum1, 1);
        sum1 += __shfl_xor_sync(0xffffffffu, sum1, 2);
        l0r = l0r * al0 + sum0;
        l1r = l1r * al1 + sum1;
        #pragma unroll
        for (int nt = 0; nt < 8; nt++) {
            o[nt][0] *= al0; o[nt][1] *= al0;
            o[nt][2] *= al1; o[nt][3] *= al1;
        }

        #pragma unroll
        for (int i = 0; i < 8; i++) {
            unsigned pa0 = pack_bf16(s[2 * i][0],     s[2 * i][1]);
            unsigned pa1 = pack_bf16(s[2 * i][2],     s[2 * i][3]);
            unsigned pa2 = pack_bf16(s[2 * i + 1][0], s[2 * i + 1][1]);
            unsigned pa3 = pack_bf16(s[2 * i + 1][2], s[2 * i + 1][3]);
            #pragma unroll
            for (int j = 0; j < 4; j++) {
                unsigned b0, b1, b2, b3;
                ldsm_x4t(b0, b1, b2, b3, Vb + i * (16 * KVROW) + j * 32);
                mma_bf16(o[2 * j],     pa0, pa1, pa2, pa3, b0, b1);
                mma_bf16(o[2 * j + 1], pa0, pa1, pa2, pa3, b2, b3);
            }
        }
    }
    #undef ISSUE

    const float inv0 = 1.0f / l0r, inv1 = 1.0f / l1r;
    #pragma unroll
    for (int nt = 0; nt < 8; nt++) {
        const int n = h * 64 + 8 * nt + 2 * t;
        const size_t r0 = (size_t)(q0 + 16 * w + g) * D_;
        const size_t r1 = (size_t)(q0 + 16 * w + g + 8) * D_;
        *(unsigned*)&ctxb[r0 + n] = pack_bf16(o[nt][0] * inv0, o[nt][1] * inv0);
        *(unsigned*)&ctxb[r1 + n] = pack_bf16(o[nt][2] * inv1, o[nt][3] * inv1);
    }
}

// ---------------- warp-per-row normalize (no barriers, no smem) ----------------
template<int N, bool AFFINE, bool ADD>
__global__ __launch_bounds__(128)
void rownorm_w(const float* __restrict__ src, const float* __restrict__ addv,
               const float* __restrict__ w, const float* __restrict__ bb,
               float* __restrict__ dst, __nv_bfloat16* __restrict__ dstb)
{
    constexpr int NV = N / 128;
    const int ln = threadIdx.x & 31;
    const int row = blockIdx.x * 4 + (threadIdx.x >> 5);
    const size_t base = (size_t)row * N;

    float4 v[NV];
    float s = 0.f;
    #pragma unroll
    for (int i = 0; i < NV; i++) {
        v[i] = *(const float4*)&src[base + i * 128 + ln * 4];
        s += v[i].x + v[i].y + v[i].z + v[i].w;
    }
    #pragma unroll
    for (int o = 16; o > 0; o >>= 1) s += __shfl_xor_sync(0xffffffffu, s, o);
    const float mean = s * (1.0f / N);
    float q = 0.f;
    #pragma unroll
    for (int i = 0; i < NV; i++) {
        float d0 = v[i].x - mean, d1 = v[i].y - mean;
        float d2 = v[i].z - mean, d3 = v[i].w - mean;
        q += d0 * d0 + d1 * d1 + d2 * d2 + d3 * d3;
    }
    #pragma unroll
    for (int o = 16; o > 0; o >>= 1) q += __shfl_xor_sync(0xffffffffu, q, o);
    const float r = rsqrtf(q * (1.0f / N) + EPSF);

    #pragma unroll
    for (int i = 0; i < NV; i++) {
        const int c = i * 128 + ln * 4;
        float y0 = (v[i].x - mean) * r, y1 = (v[i].y - mean) * r;
        float y2 = (v[i].z - mean) * r, y3 = (v[i].w - mean) * r;
        if (AFFINE) {
            float4 ww = *(const float4*)&w[c];
            float4 bv = *(const float4*)&bb[c];
            y0 = y0 * ww.x + bv.x; y1 = y1 * ww.y + bv.y;
            y2 = y2 * ww.z + bv.z; y3 = y3 * ww.w + bv.w;
        }
        if (ADD) {
            float4 av = *(const float4*)&addv[base + c];
            y0 += av.x; y1 += av.y; y2 += av.z; y3 += av.w;
        }
        if (dst) {
            float4 ov = {y0, y1, y2, y3};
            *(float4*)&dst[base + c] = ov;
        }
        if (dstb) {
            uint2 ob;
            ob.x = pack_bf16(y0, y1);
            ob.y = pack_bf16(y2, y3);
            *(uint2*)&dstb[base + c] = ob;
        }
    }
}

// ---------------- cdist to prototypes, min over P, logits ----------------
__global__ __launch_bounds__(128)
void cdist_logits(const float* __restrict__ z, const float* __restrict__ hi,
                  const float* __restrict__ neg, float* __restrict__ out)
{
    __shared__ float zr[Q_];
    const int b = blockIdx.x, t = threadIdx.x;
    const int ln = t & 31, wv = t >> 5;
    zr[t] = z[(size_t)b * Q_ + t];
    __syncthreads();
    const int slot = (wv & 1) * 32 + ln;
    const float* pb = (wv < 2) ? hi : neg;
    float d = 3.4e38f;
    if (slot < P_) {
        const float* p = pb + (size_t)slot * Q_;
        float s = 0.f;
        #pragma unroll 8
        for (int k = 0; k < Q_; k++) { float df = zr[k] - p[k]; s = fmaf(df, df, s); }
        d = sqrtf(s);
    }
    #pragma unroll
    for (int o = 16; o > 0; o >>= 1) d = fminf(d, __shfl_xor_sync(0xffffffffu, d, o));
    __shared__ float mins[4];
    if (ln == 0) mins[wv] = d;
    __syncthreads();
    if (t == 0) out[b * 2 + 1] = -fminf(mins[0], mins[1]);
    if (t == 64) out[b * 2 + 0] = -fminf(mins[2], mins[3]);
}

// ---------------- host driver ----------------
extern "C" void kernel_launch(void* const* d_in, const int* in_sizes, int n_in,
                              void* d_out, int out_size)
{
    const float* x        = (const float*)d_in[0];
    const float* reduce_w = (const float*)d_in[1];
    const float* reduce_b = (const float*)d_in[2];
    const float* in_w     = (const float*)d_in[3];
    const float* in_b     = (const float*)d_in[4];
    const float* out_w    = (const float*)d_in[5];
    const float* out_b    = (const float*)d_in[6];
    const float* ff1_w    = (const float*)d_in[7];
    const float* ff1_b    = (const float*)d_in[8];
    const float* ff2_w    = (const float*)d_in[9];
    const float* ff2_b    = (const float*)d_in[10];
    const float* ln1_w    = (const float*)d_in[11];
    const float* ln1_b    = (const float*)d_in[12];
    const float* ln2_w    = (const float*)d_in[13];
    const float* ln2_b    = (const float*)d_in[14];
    const float* mlp_w1   = (const float*)d_in[15];
    const float* mlp_b1   = (const float*)d_in[16];
    const float* mlp_w2   = (const float*)d_in[17];
    const float* mlp_b2   = (const float*)d_in[18];
    const float* mlp_w3   = (const float*)d_in[19];
    const float* mlp_b3   = (const float*)d_in[20];
    const float* highlights = (const float*)d_in[21];
    const float* negatives  = (const float*)d_in[22];
    float* out = (float*)d_out;

    float *feat0, *feat, *buf1, *buf2, *z;
    __nv_bfloat16 *wbf, *qkvb, *xb, *ab1, *ab2, *ab3;
    cudaGetSymbolAddress((void**)&feat0, g_feat0);
    cudaGetSymbolAddress((void**)&feat,  g_feat);
    cudaGetSymbolAddress((void**)&buf1,  g_buf1);
    cudaGetSymbolAddress((void**)&buf2,  g_buf2);
    cudaGetSymbolAddress((void**)&qkvb,  g_qkvb);
    cudaGetSymbolAddress((void**)&xb,    g_xb);
    cudaGetSymbolAddress((void**)&ab1,   g_ab1);
    cudaGetSymbolAddress((void**)&ab2,   g_ab2);
    cudaGetSymbolAddress((void**)&ab3,   g_ab3);
    cudaGetSymbolAddress((void**)&z,     g_z);
    cudaGetSymbolAddress((void**)&wbf,   g_wbf);

    cudaFuncSetAttribute(attn_fused, cudaFuncAttributeMaxDynamicSharedMemorySize, ATTN_SMEM);
    cudaFuncSetAttribute(attn_fused, cudaFuncAttributePreferredSharedMemoryCarveout, 100);
    const int SM64  = 3 * (128 + 64) * 80;    // 46080
    const int SM128 = 3 * (128 + 128) * 80;   // 61440
    cudaFuncSetAttribute(gemm_bf16<64, 0, 0>,  cudaFuncAttributeMaxDynamicSharedMemorySize, SM64);
    cudaFuncSetAttribute(gemm_bf16<128, 0, 1>, cudaFuncAttributeMaxDynamicSharedMemorySize, SM128);
    cudaFuncSetAttribute(gemm_bf16<64, 2, 0>,  cudaFuncAttributeMaxDynamicSharedMemorySize, SM64);
    cudaFuncSetAttribute(gemm_bf16<64, 1, 2>,  cudaFuncAttributeMaxDynamicSharedMemorySize, SM64);
    cudaFuncSetAttribute(gemm_bf16<64, 0, 0>,  cudaFuncAttributePreferredSharedMemoryCarveout, 100);
    cudaFuncSetAttribute(gemm_bf16<128, 0, 1>, cudaFuncAttributePreferredSharedMemoryCarveout, 100);
    cudaFuncSetAttribute(gemm_bf16<64, 2, 0>,  cudaFuncAttributePreferredSharedMemoryCarveout, 100);
    cudaFuncSetAttribute(gemm_bf16<64, 1, 2>,  cudaFuncAttributePreferredSharedMemoryCarveout, 100);

    // ---- convert all weights + x to bf16 in one launch ----
    Cvt9 cv;
    const float* srcs[9] = {reduce_w, in_w, out_w, ff1_w, ff2_w, mlp_w1, mlp_w2, mlp_w3, x};
    __nv_bfloat16* dsts[9] = {wbf + OFF_RED, wbf + OFF_IN, wbf + OFF_OUT, wbf + OFF_FF1,
                              wbf + OFF_FF2, wbf + OFF_M1, wbf + OFF_M2, wbf + OFF_M3, xb};
    const int n4s[9] = {D_ * DIN_ / 4, L_ * 3 * D_ * D_ / 4, L_ * D_ * D_ / 4,
                        L_ * D_ * D_ / 4, L_ * D_ * D_ / 4, D_ * D_ / 4, D_ * D_ / 4,
                        Q_ * D_ / 4, B_ * DIN_ / 4};
    cv.cum[0] = 0;
    for (int i = 0; i < 9; i++) {
        cv.s[i] = srcs[i];
        cv.d[i] = dsts[i];
        cv.cum[i + 1] = cv.cum[i] + n4s[i];
    }
    cvt_bf16_all<<<(cv.cum[9] + 255) / 256, 256>>>(cv);

    // feat0 = inorm(x @ reduce_w^T + b)
    gemm_bf16<64, 0, 0><<<dim3(D_ / 64, B_ / 128), 256, SM64>>>(
        xb, wbf + OFF_RED, reduce_b, nullptr, buf1, DIN_, D_);
    rownorm_w<D_, false, false><<<B_ / 4, 128>>>(buf1, nullptr, nullptr, nullptr, feat0, ab1);

    const float* featPrev = feat0;
    for (int l = 0; l < L_; l++) {
        gemm_bf16<128, 0, 1><<<dim3(3 * D_ / 128, B_ / 128), 256, SM128>>>(
            ab1, wbf + OFF_IN + (size_t)l * 3 * D_ * D_, in_b + l * 3 * D_, nullptr,
            qkvb, D_, 3 * D_);
        attn_fused<<<dim3(B_ / 64, H_), 128, ATTN_SMEM>>>(qkvb, ab3);
        gemm_bf16<64, 2, 0><<<dim3(D_ / 64, B_ / 128), 256, SM64>>>(
            ab3, wbf + OFF_OUT + (size_t)l * D_ * D_, out_b + l * D_, featPrev, buf1, D_, D_);
        rownorm_w<D_, true, false><<<B_ / 4, 128>>>(buf1, nullptr, ln1_w + l * D_,
                                                    ln1_b + l * D_, feat, ab1);
        gemm_bf16<64, 1, 2><<<dim3(D_ / 64, B_ / 128), 256, SM64>>>(
            ab1, wbf + OFF_FF1 + (size_t)l * D_ * D_, ff1_b + l * D_, nullptr, ab2, D_, D_);
        gemm_bf16<64, 2, 0><<<dim3(D_ / 64, B_ / 128), 256, SM64>>>(
            ab2, wbf + OFF_FF2 + (size_t)l * D_ * D_, ff2_b + l * D_, feat, buf1, D_, D_);
        rownorm_w<D_, true, false><<<B_ / 4, 128>>>(buf1, nullptr, ln2_w + l * D_,
                                                    ln2_b + l * D_, feat, ab1);
        featPrev = feat;
    }

    rownorm_w<D_, false, true><<<B_ / 4, 128>>>(feat, feat0, nullptr, nullptr, nullptr, ab1);

    gemm_bf16<64, 1, 2><<<dim3(D_ / 64, B_ / 128), 256, SM64>>>(
        ab1, wbf + OFF_M1, mlp_b1, nullptr, ab2, D_, D_);
    gemm_bf16<64, 1, 2><<<dim3(D_ / 64, B_ / 128), 256, SM64>>>(
        ab2, wbf + OFF_M2, mlp_b2, nullptr, ab3, D_, D_);
    gemm_bf16<64, 0, 0><<<dim3(Q_ / 64, B_ / 128), 256, SM64>>>(
        ab3, wbf + OFF_M3, mlp_b3, nullptr, buf2, D_, Q_);
    rownorm_w<Q_, false, false><<<B_ / 4, 128>>>(buf2, nullptr, nullptr, nullptr, z, nullptr);

    cdist_logits<<<B_, 128>>>(z, highlights, negatives, out);
}

// round 14
// speedup vs baseline: 1.1133x; 1.0711x over previous
#include <cuda_runtime.h>
#include <cuda_bf16.h>
#include <math.h>

#define B_   2048
#define DIN_ 768
#define D_   512
#define H_   8
#define HD_  64
#define L_   3
#define P_   40
#define Q_   128
#define EPSF 1e-5f

// ---------------- scratch (device globals; no allocation allowed) ----------------
__device__ float g_feat0[B_ * D_];
__device__ float g_feat [B_ * D_];
__device__ float g_buf1 [B_ * D_];
__device__ float g_buf2 [B_ * D_];
__device__ __nv_bfloat16 g_qkvb[B_ * 3 * D_];   // bf16 qkv (q pre-scaled by 1/8)
__device__ __nv_bfloat16 g_xb  [B_ * DIN_];     // bf16 copy of x
__device__ __nv_bfloat16 g_ab1 [B_ * D_];
__device__ __nv_bfloat16 g_ab2 [B_ * D_];
__device__ __nv_bfloat16 g_ab3 [B_ * D_];
__device__ __nv_bfloat16 g_wbf[5800000];         // bf16 weight pool

#define OFF_RED  0
#define OFF_IN   (OFF_RED + D_ * DIN_)
#define OFF_OUT  (OFF_IN + L_ * 3 * D_ * D_)
#define OFF_FF1  (OFF_OUT + L_ * D_ * D_)
#define OFF_FF2  (OFF_FF1 + L_ * D_ * D_)
#define OFF_M1   (OFF_FF2 + L_ * D_ * D_)
#define OFF_M2   (OFF_M1 + D_ * D_)
#define OFF_M3   (OFF_M2 + D_ * D_)

// ---------------- helpers ----------------
__device__ __forceinline__ void mma_bf16(float* c, unsigned a0, unsigned a1,
                                         unsigned a2, unsigned a3,
                                         unsigned b0, unsigned b1) {
    asm volatile(
        "mma.sync.aligned.m16n8k16.row.col.f32.bf16.bf16.f32 "
        "{%0,%1,%2,%3}, {%4,%5,%6,%7}, {%8,%9}, {%0,%1,%2,%3};"
        : "+f"(c[0]), "+f"(c[1]), "+f"(c[2]), "+f"(c[3])
        : "r"(a0), "r"(a1), "r"(a2), "r"(a3), "r"(b0), "r"(b1));
}
__device__ __forceinline__ unsigned pack_bf16(float lo, float hi) {
    unsigned r; asm("cvt.rn.bf16x2.f32 %0, %1, %2;" : "=r"(r) : "f"(hi), "f"(lo));
    return r;
}
__device__ __forceinline__ void ldsm_x4(unsigned& a, unsigned& b, unsigned& c,
                                        unsigned& d, unsigned p) {
    asm volatile("ldmatrix.sync.aligned.m8n8.x4.shared.b16 {%0,%1,%2,%3}, [%4];"
                 : "=r"(a), "=r"(b), "=r"(c), "=r"(d) : "r"(p));
}
__device__ __forceinline__ void ldsm_x4t(unsigned& a, unsigned& b, unsigned& c,
                                         unsigned& d, unsigned p) {
    asm volatile("ldmatrix.sync.aligned.m8n8.x4.trans.shared.b16 {%0,%1,%2,%3}, [%4];"
                 : "=r"(a), "=r"(b), "=r"(c), "=r"(d) : "r"(p));
}
__device__ __forceinline__ void cp16(unsigned dst, const void* src) {
    asm volatile("cp.async.cg.shared.global [%0], [%1], 16;" :: "r"(dst), "l"(src));
}

// ---------------- merged fp32 -> bf16 conversion (9 segments, 1 launch) ----------------
struct Cvt9 {
    const float* s[9];
    __nv_bfloat16* d[9];
    int cum[10];
};
__global__ __launch_bounds__(256)
void cvt_bf16_all(Cvt9 a)
{
    int gid = blockIdx.x * 256 + threadIdx.x;
    if (gid >= a.cum[9]) return;
    int seg = 0;
    #pragma unroll
    for (int i = 1; i < 9; i++) if (gid >= a.cum[i]) seg = i;
    int idx = gid - a.cum[seg];
    float4 v = ((const float4*)a.s[seg])[idx];
    uint2 r;
    r.x = pack_bf16(v.x, v.y);
    r.y = pack_bf16(v.z, v.w);
    ((uint2*)a.d[seg])[idx] = r;
}

// ============ bf16 MMA GEMM: 4-stage cp.async, 1 sync/tile, ldmatrix ============
// A:[M,K] bf16, W:[N,K] bf16, C:[M,N]. BM=128, BK=32, BN in {64, 192}.
// EPI: 0 = bias, 1 = bias+relu, 2 = bias+residual(fp32)
// OUT: 0 = fp32 ; 1 = bf16 with cols<512 scaled by 0.125 (qkv) ; 2 = bf16
template<int BN, int EPI, int OUT>
__global__ __launch_bounds__(256, (BN > 128) ? 1 : 2)
void gemm_bf16(const __nv_bfloat16* __restrict__ A, const __nv_bfloat16* __restrict__ W,
               const float* __restrict__ bias, const float* __restrict__ res,
               void* __restrict__ Cv, int K, int ldc)
{
    constexpr int NT = BN / 16;
    constexpr int NW = BN / 64;               // W staging iterations (64 rows each)
    constexpr int TROWS = 128 + BN;
    constexpr unsigned SSZ = TROWS * 80;
    extern __shared__ unsigned char smx[];
    const unsigned smb = (unsigned)__cvta_generic_to_shared(smx);

    const int tid = threadIdx.x;
    const int w = tid >> 5, ln = tid & 31, g = ln >> 2, t = ln & 3;
    const int wm = (w >> 1) * 32, wn = (w & 1) * (BN / 2);
    const int m0 = blockIdx.y * 128, n0 = blockIdx.x * BN;

    // chunk staging: 4 threads per row, 16B each
    const int arow = tid >> 2;                // 0..63
    const int aoff = (tid & 3) * 16;
    const char* apA0 = (const char*)(A + (size_t)(m0 + arow) * K) + aoff;
    const char* apA1 = (const char*)(A + (size_t)(m0 + arow + 64) * K) + aoff;
    const char* apW[NW];
    #pragma unroll
    for (int i = 0; i < NW; i++)
        apW[i] = (const char*)(W + (size_t)(n0 + arow + 64 * i) * K) + aoff;
    const unsigned sA0 = (unsigned)(arow * 80 + aoff);
    const unsigned sA1 = sA0 + 64 * 80;

    const unsigned aAddr = (wm + (ln & 7) + ((ln >> 3) & 1) * 8) * 80 + (ln >> 4) * 16;
    const unsigned wAddr = 128 * 80 + (wn + (ln & 7) + (ln >> 4) * 8) * 80
                         + ((ln >> 3) & 1) * 16;

    float acc[2][NT][4];
    #pragma unroll
    for (int mt = 0; mt < 2; mt++)
        #pragma unroll
        for (int nt = 0; nt < NT; nt++)
            #pragma unroll
            for (int i = 0; i < 4; i++) acc[mt][nt][i] = 0.f;

    const int NKT = K / 32;

    #define GISSUE(kt, slot) do {                                            \
        unsigned bs = smb + (unsigned)(slot) * SSZ;                          \
        cp16(bs + sA0, apA0 + (size_t)(kt) * 64);                            \
        cp16(bs + sA1, apA1 + (size_t)(kt) * 64);                            \
        _Pragma("unroll")                                                    \
        for (int i_ = 0; i_ < NW; i_++)                                      \
            cp16(bs + 128 * 80 + sA0 + (unsigned)(i_ * 64 * 80),             \
                 apW[i_] + (size_t)(kt) * 64);                               \
        asm volatile("cp.async.commit_group;");                              \
    } while (0)

    GISSUE(0, 0);
    GISSUE(1, 1);
    GISSUE(2, 2);

    for (int kt = 0; kt < NKT; kt++) {
        const int rem = NKT - 1 - kt;
        if (rem >= 2)      asm volatile("cp.async.wait_group 2;");
        else if (rem == 1) asm volatile("cp.async.wait_group 1;");
        else               asm volatile("cp.async.wait_group 0;");
        __syncthreads();
        if (kt + 3 < NKT) GISSUE(kt + 3, (kt + 3) & 3);
        const unsigned base = smb + (unsigned)(kt & 3) * SSZ;
        #pragma unroll
        for (int kg = 0; kg < 2; kg++) {
            unsigned a[2][4];
            ldsm_x4(a[0][0], a[0][1], a[0][2], a[0][3], base + aAddr + kg * 32);
            ldsm_x4(a[1][0], a[1][1], a[1][2], a[1][3], base + aAddr + 16 * 80 + kg * 32);
            #pragma unroll
            for (int ng = 0; ng < NT / 2; ng++) {
                unsigned b0, b1, b2, b3;
                ldsm_x4(b0, b1, b2, b3, base + wAddr + ng * (16 * 80) + kg * 32);
                mma_bf16(acc[0][2 * ng],     a[0][0], a[0][1], a[0][2], a[0][3], b0, b1);
                mma_bf16(acc[0][2 * ng + 1], a[0][0], a[0][1], a[0][2], a[0][3], b2, b3);
                mma_bf16(acc[1][2 * ng],     a[1][0], a[1][1], a[1][2], a[1][3], b0, b1);
                mma_bf16(acc[1][2 * ng + 1], a[1][0], a[1][1], a[1][2], a[1][3], b2, b3);
            }
        }
    }
    #undef GISSUE

    #pragma unroll
    for (int mt = 0; mt < 2; mt++) {
        const int r0 = m0 + wm + 16 * mt + g;
        #pragma unroll
        for (int nt = 0; nt < NT; nt++) {
            const int n = n0 + wn + 8 * nt + 2 * t;
            #pragma unroll
            for (int half = 0; half < 2; half++) {
                const size_t ro = (size_t)(r0 + 8 * half) * ldc;
                float2 v = { acc[mt][nt][2 * half], acc[mt][nt][2 * half + 1] };
                if (bias) { v.x += bias[n]; v.y += bias[n + 1]; }
                if (EPI == 1) { v.x = fmaxf(v.x, 0.f); v.y = fmaxf(v.y, 0.f); }
                if (EPI == 2) { v.x += res[ro + n]; v.y += res[ro + n + 1]; }
                if (OUT == 0) {
                    *(float2*)&((float*)Cv)[ro + n] = v;
                } else if (OUT == 1) {
                    const float sc = (n < 512) ? 0.125f : 1.0f;
                    *(unsigned*)&((__nv_bfloat16*)Cv)[ro + n] = pack_bf16(v.x * sc, v.y * sc);
                } else {
                    *(unsigned*)&((__nv_bfloat16*)Cv)[ro + n] = pack_bf16(v.x, v.y);
                }
            }
        }
    }
}

// ================= fused flash attention: 1 sync per K-tile (R13 proven) =============
#define KVROW 144
#define STG   (128 * KVROW)
#define ATTN_SMEM (4 * STG)

__global__ __launch_bounds__(128, 3)
void attn_fused(const __nv_bfloat16* __restrict__ qkvb, __nv_bfloat16* __restrict__ ctxb)
{
    extern __shared__ unsigned char sm[];
    const unsigned smb = (unsigned)__cvta_generic_to_shared(sm);
    const int tid = threadIdx.x;
    const int w = tid >> 5, ln = tid & 31, g = ln >> 2, t = ln & 3;
    const int h = blockIdx.y;
    const int q0 = blockIdx.x * 64;
    const char* qb = (const char*)qkvb;

    {
        const int r = tid >> 1;
        const char* src = qb + (size_t)(q0 + r) * 3072 + h * 128 + (tid & 1) * 64;
        unsigned dst = smb + r * KVROW + (tid & 1) * 64;
        cp16(dst, src); cp16(dst + 16, src + 16);
        cp16(dst + 32, src + 32); cp16(dst + 48, src + 48);
    }
    asm volatile("cp.async.commit_group;");
    asm volatile("cp.async.wait_group 0;");
    __syncthreads();
    unsigned qa[4][4];
    {
        const unsigned qaddr = smb + (16 * w + (ln & 7) + ((ln >> 3) & 1) * 8) * KVROW
                             + (ln >> 4) * 16;
        #pragma unroll
        for (int kg = 0; kg < 4; kg++)
            ldsm_x4(qa[kg][0], qa[kg][1], qa[kg][2], qa[kg][3], qaddr + kg * 32);
    }
    __syncthreads();

    const unsigned koff = ((ln & 7) + ((ln >> 4) << 3)) * KVROW + ((ln >> 3) & 1) * 16;
    const unsigned voff = ((ln & 7) + ((ln >> 3) & 1) * 8) * KVROW + (ln >> 4) * 16;

    #define ISSUE(ktg, buf) do {                                                   \
        unsigned kd = smb + (buf) * (2 * STG) + tid * KVROW;                       \
        const char* ks = qb + (size_t)((ktg) * 128 + tid) * 3072 + 1024 + h * 128; \
        _Pragma("unroll")                                                          \
        for (int c = 0; c < 8; c++) {                                              \
            cp16(kd + c * 16, ks + c * 16);                                        \
            cp16(kd + STG + c * 16, ks + 1024 + c * 16);                           \
        }                                                                          \
        asm volatile("cp.async.commit_group;");                                    \
    } while (0)

    float m0r = -1e30f, m1r = -1e30f, l0r = 0.f, l1r = 0.f;
    float o[8][4];
    #pragma unroll
    for (int nt = 0; nt < 8; nt++)
        #pragma unroll
        for (int i = 0; i < 4; i++) o[nt][i] = 0.f;

    ISSUE(0, 0);

    for (int kt = 0; kt < 16; kt++) {
        const int buf = kt & 1;
        asm volatile("cp.async.wait_group 0;");
        __syncthreads();
        if (kt < 15) ISSUE(kt + 1, buf ^ 1);
        const unsigned Kb = smb + buf * (2 * STG) + koff;
        const unsigned Vb = smb + buf * (2 * STG) + STG + voff;

        float s[16][4];
        #pragma unroll
        for (int nt = 0; nt < 16; nt++)
            #pragma unroll
            for (int i = 0; i < 4; i++) s[nt][i] = 0.f;
        #pragma unroll
        for (int j = 0; j < 8; j++) {
            #pragma unroll
            for (int kg = 0; kg < 4; kg++) {
                unsigned b0, b1, b2, b3;
                ldsm_x4(b0, b1, b2, b3, Kb + j * (16 * KVROW) + kg * 32);
                mma_bf16(s[2 * j],     qa[kg][0], qa[kg][1], qa[kg][2], qa[kg][3], b0, b1);
                mma_bf16(s[2 * j + 1], qa[kg][0], qa[kg][1], qa[kg][2], qa[kg][3], b2, b3);
            }
        }

        float mx0 = -1e30f, mx1 = -1e30f;
        #pragma unroll
        for (int nt = 0; nt < 16; nt++) {
            mx0 = fmaxf(mx0, fmaxf(s[nt][0], s[nt][1]));
            mx1 = fmaxf(mx1, fmaxf(s[nt][2], s[nt][3]));
        }
        mx0 = fmaxf(mx0, __shfl_xor_sync(0xffffffffu, mx0, 1));
        mx0 = fmaxf(mx0, __shfl_xor_sync(0xffffffffu, mx0, 2));
        mx1 = fmaxf(mx1, __shfl_xor_sync(0xffffffffu, mx1, 1));
        mx1 = fmaxf(mx1, __shfl_xor_sync(0xffffffffu, mx1, 2));
        const float mn0 = fmaxf(m0r, mx0), mn1 = fmaxf(m1r, mx1);
        const float al0 = __expf(m0r - mn0), al1 = __expf(m1r - mn1);
        m0r = mn0; m1r = mn1;
        float sum0 = 0.f, sum1 = 0.f;
        #pragma unroll
        for (int nt = 0; nt < 16; nt++) {
            s[nt][0] = __expf(s[nt][0] - mn0);
            s[nt][1] = __expf(s[nt][1] - mn0);
            s[nt][2] = __expf(s[nt][2] - mn1);
            s[nt][3] = __expf(s[nt][3] - mn1);
            sum0 += s[nt][0] + s[nt][1];
            sum1 += s[nt][2] + s[nt][3];
        }
        sum0 += __shfl_xor_sync(0xffffffffu, sum0, 1);
        sum0 += __shfl_xor_sync(0xffffffffu, sum0, 2);
        sum1 += __shfl_xor_sync(0xffffffffu, sum1, 1);
        sum1 += __shfl_xor_sync(0xffffffffu, sum1, 2);
        l0r = l0r * al0 + sum0;
        l1r = l1r * al1 + sum1;
        #pragma unroll
        for (int nt = 0; nt < 8; nt++) {
            o[nt][0] *= al0; o[nt][1] *= al0;
            o[nt][2] *= al1; o[nt][3] *= al1;
        }

        #pragma unroll
        for (int i = 0; i < 8; i++) {
            unsigned pa0 = pack_bf16(s[2 * i][0],     s[2 * i][1]);
            unsigned pa1 = pack_bf16(s[2 * i][2],     s[2 * i][3]);
            unsigned pa2 = pack_bf16(s[2 * i + 1][0], s[2 * i + 1][1]);
            unsigned pa3 = pack_bf16(s[2 * i + 1][2], s[2 * i + 1][3]);
            #pragma unroll
            for (int j = 0; j < 4; j++) {
                unsigned b0, b1, b2, b3;
                ldsm_x4t(b0, b1, b2, b3, Vb + i * (16 * KVROW) + j * 32);
                mma_bf16(o[2 * j],     pa0, pa1, pa2, pa3, b0, b1);
                mma_bf16(o[2 * j + 1], pa0, pa1, pa2, pa3, b2, b3);
            }
        }
    }
    #undef ISSUE

    const float inv0 = 1.0f / l0r, inv1 = 1.0f / l1r;
    #pragma unroll
    for (int nt = 0; nt < 8; nt++) {
        const int n = h * 64 + 8 * nt + 2 * t;
        const size_t r0 = (size_t)(q0 + 16 * w + g) * D_;
        const size_t r1 = (size_t)(q0 + 16 * w + g + 8) * D_;
        *(unsigned*)&ctxb[r0 + n] = pack_bf16(o[nt][0] * inv0, o[nt][1] * inv0);
        *(unsigned*)&ctxb[r1 + n] = pack_bf16(o[nt][2] * inv1, o[nt][3] * inv1);
    }
}

// ---------------- warp-per-row normalize (no barriers, no smem) ----------------
template<int N, bool AFFINE, bool ADD>
__global__ __launch_bounds__(128)
void rownorm_w(const float* __restrict__ src, const float* __restrict__ addv,
               const float* __restrict__ w, const float* __restrict__ bb,
               float* __restrict__ dst, __nv_bfloat16* __restrict__ dstb)
{
    constexpr int NV = N / 128;
    const int ln = threadIdx.x & 31;
    const int row = blockIdx.x * 4 + (threadIdx.x >> 5);
    const size_t base = (size_t)row * N;

    float4 v[NV];
    float s = 0.f;
    #pragma unroll
    for (int i = 0; i < NV; i++) {
        v[i] = *(const float4*)&src[base + i * 128 + ln * 4];
        s += v[i].x + v[i].y + v[i].z + v[i].w;
    }
    #pragma unroll
    for (int o = 16; o > 0; o >>= 1) s += __shfl_xor_sync(0xffffffffu, s, o);
    const float mean = s * (1.0f / N);
    float q = 0.f;
    #pragma unroll
    for (int i = 0; i < NV; i++) {
        float d0 = v[i].x - mean, d1 = v[i].y - mean;
        float d2 = v[i].z - mean, d3 = v[i].w - mean;
        q += d0 * d0 + d1 * d1 + d2 * d2 + d3 * d3;
    }
    #pragma unroll
    for (int o = 16; o > 0; o >>= 1) q += __shfl_xor_sync(0xffffffffu, q, o);
    const float r = rsqrtf(q * (1.0f / N) + EPSF);

    #pragma unroll
    for (int i = 0; i < NV; i++) {
        const int c = i * 128 + ln * 4;
        float y0 = (v[i].x - mean) * r, y1 = (v[i].y - mean) * r;
        float y2 = (v[i].z - mean) * r, y3 = (v[i].w - mean) * r;
        if (AFFINE) {
            float4 ww = *(const float4*)&w[c];
            float4 bv = *(const float4*)&bb[c];
            y0 = y0 * ww.x + bv.x; y1 = y1 * ww.y + bv.y;
            y2 = y2 * ww.z + bv.z; y3 = y3 * ww.w + bv.w;
        }
        if (ADD) {
            float4 av = *(const float4*)&addv[base + c];
            y0 += av.x; y1 += av.y; y2 += av.z; y3 += av.w;
        }
        if (dst) {
            float4 ov = {y0, y1, y2, y3};
            *(float4*)&dst[base + c] = ov;
        }
        if (dstb) {
            uint2 ob;
            ob.x = pack_bf16(y0, y1);
            ob.y = pack_bf16(y2, y3);
            *(uint2*)&dstb[base + c] = ob;
        }
    }
}

// ---------------- fused InstanceNorm + cdist + logits ----------------
__global__ __launch_bounds__(128)
void cdist_logits(const float* __restrict__ zraw, const float* __restrict__ hi,
                  const float* __restrict__ neg, float* __restrict__ out)
{
    __shared__ float zr[Q_];
    __shared__ float red[8];
    const int b = blockIdx.x, t = threadIdx.x;
    const int ln = t & 31, wv = t >> 5;

    // ---- in-block InstanceNorm of the 128-wide row ----
    float v = zraw[(size_t)b * Q_ + t];
    float s = v, s2 = v * v;
    #pragma unroll
    for (int o = 16; o > 0; o >>= 1) {
        s  += __shfl_xor_sync(0xffffffffu, s,  o);
        s2 += __shfl_xor_sync(0xffffffffu, s2, o);
    }
    if (ln == 0) { red[wv] = s; red[4 + wv] = s2; }
    __syncthreads();
    s  = red[0] + red[1] + red[2] + red[3];
    s2 = red[4] + red[5] + red[6] + red[7];
    const float mean = s * (1.0f / Q_);
    const float var  = s2 * (1.0f / Q_) - mean * mean;
    const float rs = rsqrtf(var + EPSF);
    zr[t] = (v - mean) * rs;
    __syncthreads();

    // ---- distances ----
    const int slot = (wv & 1) * 32 + ln;
    const float* pb = (wv < 2) ? hi : neg;
    float d = 3.4e38f;
    if (slot < P_) {
        const float* p = pb + (size_t)slot * Q_;
        float acc = 0.f;
        #pragma unroll 8
        for (int k = 0; k < Q_; k++) { float df = zr[k] - p[k]; acc = fmaf(df, df, acc); }
        d = sqrtf(acc);
    }
    #pragma unroll
    for (int o = 16; o > 0; o >>= 1) d = fminf(d, __shfl_xor_sync(0xffffffffu, d, o));
    if (ln == 0) red[wv] = d;
    __syncthreads();
    if (t == 0) out[b * 2 + 1] = -fminf(red[0], red[1]);
    if (t == 64) out[b * 2 + 0] = -fminf(red[2], red[3]);
}

// ---------------- host driver ----------------
extern "C" void kernel_launch(void* const* d_in, const int* in_sizes, int n_in,
                              void* d_out, int out_size)
{
    const float* x        = (const float*)d_in[0];
    const float* reduce_w = (const float*)d_in[1];
    const float* reduce_b = (const float*)d_in[2];
    const float* in_w     = (const float*)d_in[3];
    const float* in_b     = (const float*)d_in[4];
    const float* out_w    = (const float*)d_in[5];
    const float* out_b    = (const float*)d_in[6];
    const float* ff1_w    = (const float*)d_in[7];
    const float* ff1_b    = (const float*)d_in[8];
    const float* ff2_w    = (const float*)d_in[9];
    const float* ff2_b    = (const float*)d_in[10];
    const float* ln1_w    = (const float*)d_in[11];
    const float* ln1_b    = (const float*)d_in[12];
    const float* ln2_w    = (const float*)d_in[13];
    const float* ln2_b    = (const float*)d_in[14];
    const float* mlp_w1   = (const float*)d_in[15];
    const float* mlp_b1   = (const float*)d_in[16];
    const float* mlp_w2   = (const float*)d_in[17];
    const float* mlp_b2   = (const float*)d_in[18];
    const float* mlp_w3   = (const float*)d_in[19];
    const float* mlp_b3   = (const float*)d_in[20];
    const float* highlights = (const float*)d_in[21];
    const float* negatives  = (const float*)d_in[22];
    float* out = (float*)d_out;

    float *feat0, *feat, *buf1, *buf2;
    __nv_bfloat16 *wbf, *qkvb, *xb, *ab1, *ab2, *ab3;
    cudaGetSymbolAddress((void**)&feat0, g_feat0);
    cudaGetSymbolAddress((void**)&feat,  g_feat);
    cudaGetSymbolAddress((void**)&buf1,  g_buf1);
    cudaGetSymbolAddress((void**)&buf2,  g_buf2);
    cudaGetSymbolAddress((void**)&qkvb,  g_qkvb);
    cudaGetSymbolAddress((void**)&xb,    g_xb);
    cudaGetSymbolAddress((void**)&ab1,   g_ab1);
    cudaGetSymbolAddress((void**)&ab2,   g_ab2);
    cudaGetSymbolAddress((void**)&ab3,   g_ab3);
    cudaGetSymbolAddress((void**)&wbf,   g_wbf);

    cudaFuncSetAttribute(attn_fused, cudaFuncAttributeMaxDynamicSharedMemorySize, ATTN_SMEM);
    cudaFuncSetAttribute(attn_fused, cudaFuncAttributePreferredSharedMemoryCarveout, 100);
    const int SM64  = 4 * (128 + 64) * 80;    // 61440
    const int SM192 = 4 * (128 + 192) * 80;   // 102400
    cudaFuncSetAttribute(gemm_bf16<64, 0, 0>,  cudaFuncAttributeMaxDynamicSharedMemorySize, SM64);
    cudaFuncSetAttribute(gemm_bf16<192, 0, 1>, cudaFuncAttributeMaxDynamicSharedMemorySize, SM192);
    cudaFuncSetAttribute(gemm_bf16<64, 2, 0>,  cudaFuncAttributeMaxDynamicSharedMemorySize, SM64);
    cudaFuncSetAttribute(gemm_bf16<64, 1, 2>,  cudaFuncAttributeMaxDynamicSharedMemorySize, SM64);
    cudaFuncSetAttribute(gemm_bf16<64, 0, 0>,  cudaFuncAttributePreferredSharedMemoryCarveout, 100);
    cudaFuncSetAttribute(gemm_bf16<192, 0, 1>, cudaFuncAttributePreferredSharedMemoryCarveout, 100);
    cudaFuncSetAttribute(gemm_bf16<64, 2, 0>,  cudaFuncAttributePreferredSharedMemoryCarveout, 100);
    cudaFuncSetAttribute(gemm_bf16<64, 1, 2>,  cudaFuncAttributePreferredSharedMemoryCarveout, 100);

    // ---- convert all weights + x to bf16 in one launch ----
    Cvt9 cv;
    const float* srcs[9] = {reduce_w, in_w, out_w, ff1_w, ff2_w, mlp_w1, mlp_w2, mlp_w3, x};
    __nv_bfloat16* dsts[9] = {wbf + OFF_RED, wbf + OFF_IN, wbf + OFF_OUT, wbf + OFF_FF1,
                              wbf + OFF_FF2, wbf + OFF_M1, wbf + OFF_M2, wbf + OFF_M3, xb};
    const int n4s[9] = {D_ * DIN_ / 4, L_ * 3 * D_ * D_ / 4, L_ * D_ * D_ / 4,
                        L_ * D_ * D_ / 4, L_ * D_ * D_ / 4, D_ * D_ / 4, D_ * D_ / 4,
                        Q_ * D_ / 4, B_ * DIN_ / 4};
    cv.cum[0] = 0;
    for (int i = 0; i < 9; i++) {
        cv.s[i] = srcs[i];
        cv.d[i] = dsts[i];
        cv.cum[i + 1] = cv.cum[i] + n4s[i];
    }
    cvt_bf16_all<<<(cv.cum[9] + 255) / 256, 256>>>(cv);

    // feat0 = inorm(x @ reduce_w^T + b)
    gemm_bf16<64, 0, 0><<<dim3(D_ / 64, B_ / 128), 256, SM64>>>(
        xb, wbf + OFF_RED, reduce_b, nullptr, buf1, DIN_, D_);
    rownorm_w<D_, false, false><<<B_ / 4, 128>>>(buf1, nullptr, nullptr, nullptr, feat0, ab1);

    const float* featPrev = feat0;
    for (int l = 0; l < L_; l++) {
        gemm_bf16<192, 0, 1><<<dim3(3 * D_ / 192, B_ / 128), 256, SM192>>>(
            ab1, wbf + OFF_IN + (size_t)l * 3 * D_ * D_, in_b + l * 3 * D_, nullptr,
            qkvb, D_, 3 * D_);
        attn_fused<<<dim3(B_ / 64, H_), 128, ATTN_SMEM>>>(qkvb, ab3);
        gemm_bf16<64, 2, 0><<<dim3(D_ / 64, B_ / 128), 256, SM64>>>(
            ab3, wbf + OFF_OUT + (size_t)l * D_ * D_, out_b + l * D_, featPrev, buf1, D_, D_);
        rownorm_w<D_, true, false><<<B_ / 4, 128>>>(buf1, nullptr, ln1_w + l * D_,
                                                    ln1_b + l * D_, feat, ab1);
        gemm_bf16<64, 1, 2><<<dim3(D_ / 64, B_ / 128), 256, SM64>>>(
            ab1, wbf + OFF_FF1 + (size_t)l * D_ * D_, ff1_b + l * D_, nullptr, ab2, D_, D_);
        gemm_bf16<64, 2, 0><<<dim3(D_ / 64, B_ / 128), 256, SM64>>>(
            ab2, wbf + OFF_FF2 + (size_t)l * D_ * D_, ff2_b + l * D_, feat, buf1, D_, D_);
        rownorm_w<D_, true, false><<<B_ / 4, 128>>>(buf1, nullptr, ln2_w + l * D_,
                                                    ln2_b + l * D_, feat, ab1);
        featPrev = feat;
    }

    rownorm_w<D_, false, true><<<B_ / 4, 128>>>(feat, feat0, nullptr, nullptr, nullptr, ab1);

    gemm_bf16<64, 1, 2><<<dim3(D_ / 64, B_ / 128), 256, SM64>>>(
        ab1, wbf + OFF_M1, mlp_b1, nullptr, ab2, D_, D_);
    gemm_bf16<64, 1, 2><<<dim3(D_ / 64, B_ / 128), 256, SM64>>>(
        ab2, wbf + OFF_M2, mlp_b2, nullptr, ab3, D_, D_);
    gemm_bf16<64, 0, 0><<<dim3(Q_ / 64, B_ / 128), 256, SM64>>>(
        ab3, wbf + OFF_M3, mlp_b3, nullptr, buf2, D_, Q_);

    cdist_logits<<<B_, 128>>>(buf2, highlights, negatives, out);
}

// round 15
// speedup vs baseline: 1.1562x; 1.0385x over previous
#include <cuda_runtime.h>
#include <cuda_bf16.h>
#include <math.h>

#define B_   2048
#define DIN_ 768
#define D_   512
#define H_   8
#define HD_  64
#define L_   3
#define P_   40
#define Q_   128
#define EPSF 1e-5f

// ---------------- scratch (device globals; no allocation allowed) ----------------
__device__ float g_feat0[B_ * D_];
__device__ float g_feat [B_ * D_];
__device__ float g_buf1 [B_ * D_];
__device__ float g_buf2 [B_ * D_];
__device__ __nv_bfloat16 g_qkvb[B_ * 3 * D_];   // bf16 qkv (q pre-scaled by 1/8)
__device__ __nv_bfloat16 g_xb  [B_ * DIN_];     // bf16 copy of x
__device__ __nv_bfloat16 g_ab1 [B_ * D_];
__device__ __nv_bfloat16 g_ab2 [B_ * D_];
__device__ __nv_bfloat16 g_ab3 [B_ * D_];
__device__ __nv_bfloat16 g_wbf[5800000];         // bf16 weight pool

#define OFF_RED  0
#define OFF_IN   (OFF_RED + D_ * DIN_)
#define OFF_OUT  (OFF_IN + L_ * 3 * D_ * D_)
#define OFF_FF1  (OFF_OUT + L_ * D_ * D_)
#define OFF_FF2  (OFF_FF1 + L_ * D_ * D_)
#define OFF_M1   (OFF_FF2 + L_ * D_ * D_)
#define OFF_M2   (OFF_M1 + D_ * D_)
#define OFF_M3   (OFF_M2 + D_ * D_)

// ---------------- helpers ----------------
__device__ __forceinline__ void mma_bf16(float* c, unsigned a0, unsigned a1,
                                         unsigned a2, unsigned a3,
                                         unsigned b0, unsigned b1) {
    asm volatile(
        "mma.sync.aligned.m16n8k16.row.col.f32.bf16.bf16.f32 "
        "{%0,%1,%2,%3}, {%4,%5,%6,%7}, {%8,%9}, {%0,%1,%2,%3};"
        : "+f"(c[0]), "+f"(c[1]), "+f"(c[2]), "+f"(c[3])
        : "r"(a0), "r"(a1), "r"(a2), "r"(a3), "r"(b0), "r"(b1));
}
__device__ __forceinline__ unsigned pack_bf16(float lo, float hi) {
    unsigned r; asm("cvt.rn.bf16x2.f32 %0, %1, %2;" : "=r"(r) : "f"(hi), "f"(lo));
    return r;
}
__device__ __forceinline__ void ldsm_x4(unsigned& a, unsigned& b, unsigned& c,
                                        unsigned& d, unsigned p) {
    asm volatile("ldmatrix.sync.aligned.m8n8.x4.shared.b16 {%0,%1,%2,%3}, [%4];"
                 : "=r"(a), "=r"(b), "=r"(c), "=r"(d) : "r"(p));
}
__device__ __forceinline__ void ldsm_x4t(unsigned& a, unsigned& b, unsigned& c,
                                         unsigned& d, unsigned p) {
    asm volatile("ldmatrix.sync.aligned.m8n8.x4.trans.shared.b16 {%0,%1,%2,%3}, [%4];"
                 : "=r"(a), "=r"(b), "=r"(c), "=r"(d) : "r"(p));
}
__device__ __forceinline__ void cp16(unsigned dst, const void* src) {
    asm volatile("cp.async.cg.shared.global [%0], [%1], 16;" :: "r"(dst), "l"(src));
}

// ---------------- merged fp32 -> bf16 conversion (9 segments, 1 launch) ----------------
struct Cvt9 {
    const float* s[9];
    __nv_bfloat16* d[9];
    int cum[10];
};
__global__ __launch_bounds__(256)
void cvt_bf16_all(Cvt9 a)
{
    int gid = blockIdx.x * 256 + threadIdx.x;
    if (gid >= a.cum[9]) return;
    int seg = 0;
    #pragma unroll
    for (int i = 1; i < 9; i++) if (gid >= a.cum[i]) seg = i;
    int idx = gid - a.cum[seg];
    float4 v = ((const float4*)a.s[seg])[idx];
    uint2 r;
    r.x = pack_bf16(v.x, v.y);
    r.y = pack_bf16(v.z, v.w);
    ((uint2*)a.d[seg])[idx] = r;
}

// ============ bf16 MMA GEMM: BK=64 (attention-layout tiles), 3-stage cp.async ============
// A:[M,K] bf16, W:[N,K] bf16, C:[M,N]. BM=128, BK=64, BN in {64, 192}.
// Row stride 144 B (same as attention KVROW — proven conflict-free fragment layout).
// EPI: 0 = bias, 1 = bias+relu, 2 = bias+residual(fp32)
// OUT: 0 = fp32 ; 1 = bf16 with cols<512 scaled by 0.125 (qkv) ; 2 = bf16
template<int BN, int EPI, int OUT>
__global__ __launch_bounds__(256, (BN > 128) ? 1 : 2)
void gemm_bf16(const __nv_bfloat16* __restrict__ A, const __nv_bfloat16* __restrict__ W,
               const float* __restrict__ bias, const float* __restrict__ res,
               void* __restrict__ Cv, int K, int ldc)
{
    constexpr int NT = BN / 16;
    constexpr int TROWS = 128 + BN;
    constexpr unsigned SSZ = TROWS * 144;
    constexpr int NCH = TROWS * 8 / 256;     // 16B chunks per thread per tile
    extern __shared__ unsigned char smx[];
    const unsigned smb = (unsigned)__cvta_generic_to_shared(smx);

    const int tid = threadIdx.x;
    const int w = tid >> 5, ln = tid & 31;
    const int g = ln >> 2, t = ln & 3;
    const int wm = (w >> 1) * 32, wn = (w & 1) * (BN / 2);
    const int m0 = blockIdx.y * 128, n0 = blockIdx.x * BN;

    // chunk staging: chunk c = tid + 256*i; row = c>>3; off = (c&7)*16
    const char* srcs[NCH];
    unsigned dsts[NCH];
    #pragma unroll
    for (int i = 0; i < NCH; i++) {
        const int c = tid + 256 * i;
        const int row = c >> 3, off = (c & 7) * 16;
        srcs[i] = (const char*)((row < 128)
                    ? (A + (size_t)(m0 + row) * K)
                    : (W + (size_t)(n0 + row - 128) * K)) + off;
        dsts[i] = (unsigned)(row * 144 + off);
    }

    // fragment addresses (attention-proven patterns, row stride 144)
    const unsigned aOff = ((ln & 7) + ((ln >> 3) & 1) * 8) * 144 + (ln >> 4) * 16;
    const unsigned wOff = 128 * 144 + ((ln & 7) + ((ln >> 4) << 3)) * 144
                        + ((ln >> 3) & 1) * 16;

    float acc[2][NT][4];
    #pragma unroll
    for (int mt = 0; mt < 2; mt++)
        #pragma unroll
        for (int nt = 0; nt < NT; nt++)
            #pragma unroll
            for (int i = 0; i < 4; i++) acc[mt][nt][i] = 0.f;

    const int NKT = K >> 6;

    #define GISSUE(kt, slot) do {                                           \
        const unsigned bs = smb + (unsigned)(slot) * SSZ;                   \
        _Pragma("unroll")                                                   \
        for (int i_ = 0; i_ < NCH; i_++)                                    \
            cp16(bs + dsts[i_], srcs[i_] + (size_t)(kt) * 128);             \
        asm volatile("cp.async.commit_group;");                             \
    } while (0)

    GISSUE(0, 0);
    GISSUE(1, 1);

    int slot = 0;
    for (int kt = 0; kt < NKT; kt++) {
        if (kt + 1 < NKT) asm volatile("cp.async.wait_group 1;");
        else              asm volatile("cp.async.wait_group 0;");
        __syncthreads();
        if (kt + 2 < NKT) {
            int s2 = slot + 2; if (s2 >= 3) s2 -= 3;
            GISSUE(kt + 2, s2);
        }
        const unsigned base = smb + (unsigned)slot * SSZ;
        slot = (slot == 2) ? 0 : slot + 1;

        #pragma unroll
        for (int kg = 0; kg < 4; kg++) {
            unsigned a[2][4];
            ldsm_x4(a[0][0], a[0][1], a[0][2], a[0][3],
                    base + (wm)      * 144 + aOff + kg * 32);
            ldsm_x4(a[1][0], a[1][1], a[1][2], a[1][3],
                    base + (wm + 16) * 144 + aOff + kg * 32);
            #pragma unroll
            for (int ng = 0; ng < NT / 2; ng++) {
                unsigned b0, b1, b2, b3;
                ldsm_x4(b0, b1, b2, b3, base + wOff + (wn + 16 * ng) * 144 + kg * 32);
                mma_bf16(acc[0][2 * ng],     a[0][0], a[0][1], a[0][2], a[0][3], b0, b1);
                mma_bf16(acc[0][2 * ng + 1], a[0][0], a[0][1], a[0][2], a[0][3], b2, b3);
                mma_bf16(acc[1][2 * ng],     a[1][0], a[1][1], a[1][2], a[1][3], b0, b1);
                mma_bf16(acc[1][2 * ng + 1], a[1][0], a[1][1], a[1][2], a[1][3], b2, b3);
            }
        }
    }
    #undef GISSUE

    #pragma unroll
    for (int mt = 0; mt < 2; mt++) {
        const int r0 = m0 + wm + 16 * mt + g;
        #pragma unroll
        for (int nt = 0; nt < NT; nt++) {
            const int n = n0 + wn + 8 * nt + 2 * t;
            #pragma unroll
            for (int half = 0; half < 2; half++) {
                const size_t ro = (size_t)(r0 + 8 * half) * ldc;
                float2 v = { acc[mt][nt][2 * half], acc[mt][nt][2 * half + 1] };
                if (bias) { v.x += bias[n]; v.y += bias[n + 1]; }
                if (EPI == 1) { v.x = fmaxf(v.x, 0.f); v.y = fmaxf(v.y, 0.f); }
                if (EPI == 2) { v.x += res[ro + n]; v.y += res[ro + n + 1]; }
                if (OUT == 0) {
                    *(float2*)&((float*)Cv)[ro + n] = v;
                } else if (OUT == 1) {
                    const float sc = (n < 512) ? 0.125f : 1.0f;
                    *(unsigned*)&((__nv_bfloat16*)Cv)[ro + n] = pack_bf16(v.x * sc, v.y * sc);
                } else {
                    *(unsigned*)&((__nv_bfloat16*)Cv)[ro + n] = pack_bf16(v.x, v.y);
                }
            }
        }
    }
}

// ================= fused flash attention: 1 sync per K-tile (proven) =============
#define KVROW 144
#define STG   (128 * KVROW)
#define ATTN_SMEM (4 * STG)

__global__ __launch_bounds__(128, 3)
void attn_fused(const __nv_bfloat16* __restrict__ qkvb, __nv_bfloat16* __restrict__ ctxb)
{
    extern __shared__ unsigned char sm[];
    const unsigned smb = (unsigned)__cvta_generic_to_shared(sm);
    const int tid = threadIdx.x;
    const int w = tid >> 5, ln = tid & 31, g = ln >> 2, t = ln & 3;
    const int h = blockIdx.y;
    const int q0 = blockIdx.x * 64;
    const char* qb = (const char*)qkvb;

    {
        const int r = tid >> 1;
        const char* src = qb + (size_t)(q0 + r) * 3072 + h * 128 + (tid & 1) * 64;
        unsigned dst = smb + r * KVROW + (tid & 1) * 64;
        cp16(dst, src); cp16(dst + 16, src + 16);
        cp16(dst + 32, src + 32); cp16(dst + 48, src + 48);
    }
    asm volatile("cp.async.commit_group;");
    asm volatile("cp.async.wait_group 0;");
    __syncthreads();
    unsigned qa[4][4];
    {
        const unsigned qaddr = smb + (16 * w + (ln & 7) + ((ln >> 3) & 1) * 8) * KVROW
                             + (ln >> 4) * 16;
        #pragma unroll
        for (int kg = 0; kg < 4; kg++)
            ldsm_x4(qa[kg][0], qa[kg][1], qa[kg][2], qa[kg][3], qaddr + kg * 32);
    }
    __syncthreads();

    const unsigned koff = ((ln & 7) + ((ln >> 4) << 3)) * KVROW + ((ln >> 3) & 1) * 16;
    const unsigned voff = ((ln & 7) + ((ln >> 3) & 1) * 8) * KVROW + (ln >> 4) * 16;

    #define ISSUE(ktg, buf) do {                                                   \
        unsigned kd = smb + (buf) * (2 * STG) + tid * KVROW;                       \
        const char* ks = qb + (size_t)((ktg) * 128 + tid) * 3072 + 1024 + h * 128; \
        _Pragma("unroll")                                                          \
        for (int c = 0; c < 8; c++) {                                              \
            cp16(kd + c * 16, ks + c * 16);                                        \
            cp16(kd + STG + c * 16, ks + 1024 + c * 16);                           \
        }                                                                          \
        asm volatile("cp.async.commit_group;");                                    \
    } while (0)

    float m0r = -1e30f, m1r = -1e30f, l0r = 0.f, l1r = 0.f;
    float o[8][4];
    #pragma unroll
    for (int nt = 0; nt < 8; nt++)
        #pragma unroll
        for (int i = 0; i < 4; i++) o[nt][i] = 0.f;

    ISSUE(0, 0);

    for (int kt = 0; kt < 16; kt++) {
        const int buf = kt & 1;
        asm volatile("cp.async.wait_group 0;");
        __syncthreads();
        if (kt < 15) ISSUE(kt + 1, buf ^ 1);
        const unsigned Kb = smb + buf * (2 * STG) + koff;
        const unsigned Vb = smb + buf * (2 * STG) + STG + voff;

        float s[16][4];
        #pragma unroll
        for (int nt = 0; nt < 16; nt++)
            #pragma unroll
            for (int i = 0; i < 4; i++) s[nt][i] = 0.f;
        #pragma unroll
        for (int j = 0; j < 8; j++) {
            #pragma unroll
            for (int kg = 0; kg < 4; kg++) {
                unsigned b0, b1, b2, b3;
                ldsm_x4(b0, b1, b2, b3, Kb + j * (16 * KVROW) + kg * 32);
                mma_bf16(s[2 * j],     qa[kg][0], qa[kg][1], qa[kg][2], qa[kg][3], b0, b1);
                mma_bf16(s[2 * j + 1], qa[kg][0], qa[kg][1], qa[kg][2], qa[kg][3], b2, b3);
            }
        }

        float mx0 = -1e30f, mx1 = -1e30f;
        #pragma unroll
        for (int nt = 0; nt < 16; nt++) {
            mx0 = fmaxf(mx0, fmaxf(s[nt][0], s[nt][1]));
            mx1 = fmaxf(mx1, fmaxf(s[nt][2], s[nt][3]));
        }
        mx0 = fmaxf(mx0, __shfl_xor_sync(0xffffffffu, mx0, 1));
        mx0 = fmaxf(mx0, __shfl_xor_sync(0xffffffffu, mx0, 2));
        mx1 = fmaxf(mx1, __shfl_xor_sync(0xffffffffu, mx1, 1));
        mx1 = fmaxf(mx1, __shfl_xor_sync(0xffffffffu, mx1, 2));
        const float mn0 = fmaxf(m0r, mx0), mn1 = fmaxf(m1r, mx1);
        const float al0 = __expf(m0r - mn0), al1 = __expf(m1r - mn1);
        m0r = mn0; m1r = mn1;
        float sum0 = 0.f, sum1 = 0.f;
        #pragma unroll
        for (int nt = 0; nt < 16; nt++) {
            s[nt][0] = __expf(s[nt][0] - mn0);
            s[nt][1] = __expf(s[nt][1] - mn0);
            s[nt][2] = __expf(s[nt][2] - mn1);
            s[nt][3] = __expf(s[nt][3] - mn1);
            sum0 += s[nt][0] + s[nt][1];
            sum1 += s[nt][2] + s[nt][3];
        }
        sum0 += __shfl_xor_sync(0xffffffffu, sum0, 1);
        sum0 += __shfl_xor_sync(0xffffffffu, sum0, 2);
        sum1 += __shfl_xor_sync(0xffffffffu, sum1, 1);
        sum1 += __shfl_xor_sync(0xffffffffu, sum1, 2);
        l0r = l0r * al0 + sum0;
        l1r = l1r * al1 + sum1;
        #pragma unroll
        for (int nt = 0; nt < 8; nt++) {
            o[nt][0] *= al0; o[nt][1] *= al0;
            o[nt][2] *= al1; o[nt][3] *= al1;
        }

        #pragma unroll
        for (int i = 0; i < 8; i++) {
            unsigned pa0 = pack_bf16(s[2 * i][0],     s[2 * i][1]);
            unsigned pa1 = pack_bf16(s[2 * i][2],     s[2 * i][3]);
            unsigned pa2 = pack_bf16(s[2 * i + 1][0], s[2 * i + 1][1]);
            unsigned pa3 = pack_bf16(s[2 * i + 1][2], s[2 * i + 1][3]);
            #pragma unroll
            for (int j = 0; j < 4; j++) {
                unsigned b0, b1, b2, b3;
                ldsm_x4t(b0, b1, b2, b3, Vb + i * (16 * KVROW) + j * 32);
                mma_bf16(o[2 * j],     pa0, pa1, pa2, pa3, b0, b1);
                mma_bf16(o[2 * j + 1], pa0, pa1, pa2, pa3, b2, b3);
            }
        }
    }
    #undef ISSUE

    const float inv0 = 1.0f / l0r, inv1 = 1.0f / l1r;
    #pragma unroll
    for (int nt = 0; nt < 8; nt++) {
        const int n = h * 64 + 8 * nt + 2 * t;
        const size_t r0 = (size_t)(q0 + 16 * w + g) * D_;
        const size_t r1 = (size_t)(q0 + 16 * w + g + 8) * D_;
        *(unsigned*)&ctxb[r0 + n] = pack_bf16(o[nt][0] * inv0, o[nt][1] * inv0);
        *(unsigned*)&ctxb[r1 + n] = pack_bf16(o[nt][2] * inv1, o[nt][3] * inv1);
    }
}

// ---------------- warp-per-row normalize (no barriers, no smem) ----------------
template<int N, bool AFFINE, bool ADD>
__global__ __launch_bounds__(128)
void rownorm_w(const float* __restrict__ src, const float* __restrict__ addv,
               const float* __restrict__ w, const float* __restrict__ bb,
               float* __restrict__ dst, __nv_bfloat16* __restrict__ dstb)
{
    constexpr int NV = N / 128;
    const int ln = threadIdx.x & 31;
    const int row = blockIdx.x * 4 + (threadIdx.x >> 5);
    const size_t base = (size_t)row * N;

    float4 v[NV];
    float s = 0.f;
    #pragma unroll
    for (int i = 0; i < NV; i++) {
        v[i] = *(const float4*)&src[base + i * 128 + ln * 4];
        s += v[i].x + v[i].y + v[i].z + v[i].w;
    }
    #pragma unroll
    for (int o = 16; o > 0; o >>= 1) s += __shfl_xor_sync(0xffffffffu, s, o);
    const float mean = s * (1.0f / N);
    float q = 0.f;
    #pragma unroll
    for (int i = 0; i < NV; i++) {
        float d0 = v[i].x - mean, d1 = v[i].y - mean;
        float d2 = v[i].z - mean, d3 = v[i].w - mean;
        q += d0 * d0 + d1 * d1 + d2 * d2 + d3 * d3;
    }
    #pragma unroll
    for (int o = 16; o > 0; o >>= 1) q += __shfl_xor_sync(0xffffffffu, q, o);
    const float r = rsqrtf(q * (1.0f / N) + EPSF);

    #pragma unroll
    for (int i = 0; i < NV; i++) {
        const int c = i * 128 + ln * 4;
        float y0 = (v[i].x - mean) * r, y1 = (v[i].y - mean) * r;
        float y2 = (v[i].z - mean) * r, y3 = (v[i].w - mean) * r;
        if (AFFINE) {
            float4 ww = *(const float4*)&w[c];
            float4 bv = *(const float4*)&bb[c];
            y0 = y0 * ww.x + bv.x; y1 = y1 * ww.y + bv.y;
            y2 = y2 * ww.z + bv.z; y3 = y3 * ww.w + bv.w;
        }
        if (ADD) {
            float4 av = *(const float4*)&addv[base + c];
            y0 += av.x; y1 += av.y; y2 += av.z; y3 += av.w;
        }
        if (dst) {
            float4 ov = {y0, y1, y2, y3};
            *(float4*)&dst[base + c] = ov;
        }
        if (dstb) {
            uint2 ob;
            ob.x = pack_bf16(y0, y1);
            ob.y = pack_bf16(y2, y3);
            *(uint2*)&dstb[base + c] = ob;
        }
    }
}

// ---------------- fused InstanceNorm + cdist + logits ----------------
__global__ __launch_bounds__(128)
void cdist_logits(const float* __restrict__ zraw, const float* __restrict__ hi,
                  const float* __restrict__ neg, float* __restrict__ out)
{
    __shared__ float zr[Q_];
    __shared__ float red[8];
    const int b = blockIdx.x, t = threadIdx.x;
    const int ln = t & 31, wv = t >> 5;

    float v = zraw[(size_t)b * Q_ + t];
    float s = v, s2 = v * v;
    #pragma unroll
    for (int o = 16; o > 0; o >>= 1) {
        s  += __shfl_xor_sync(0xffffffffu, s,  o);
        s2 += __shfl_xor_sync(0xffffffffu, s2, o);
    }
    if (ln == 0) { red[wv] = s; red[4 + wv] = s2; }
    __syncthreads();
    s  = red[0] + red[1] + red[2] + red[3];
    s2 = red[4] + red[5] + red[6] + red[7];
    const float mean = s * (1.0f / Q_);
    const float var  = s2 * (1.0f / Q_) - mean * mean;
    const float rs = rsqrtf(var + EPSF);
    zr[t] = (v - mean) * rs;
    __syncthreads();

    const int slot = (wv & 1) * 32 + ln;
    const float* pb = (wv < 2) ? hi : neg;
    float d = 3.4e38f;
    if (slot < P_) {
        const float* p = pb + (size_t)slot * Q_;
        float acc = 0.f;
        #pragma unroll 8
        for (int k = 0; k < Q_; k++) { float df = zr[k] - p[k]; acc = fmaf(df, df, acc); }
        d = sqrtf(acc);
    }
    #pragma unroll
    for (int o = 16; o > 0; o >>= 1) d = fminf(d, __shfl_xor_sync(0xffffffffu, d, o));
    if (ln == 0) red[wv] = d;
    __syncthreads();
    if (t == 0) out[b * 2 + 1] = -fminf(red[0], red[1]);
    if (t == 64) out[b * 2 + 0] = -fminf(red[2], red[3]);
}

// ---------------- host driver ----------------
extern "C" void kernel_launch(void* const* d_in, const int* in_sizes, int n_in,
                              void* d_out, int out_size)
{
    const float* x        = (const float*)d_in[0];
    const float* reduce_w = (const float*)d_in[1];
    const float* reduce_b = (const float*)d_in[2];
    const float* in_w     = (const float*)d_in[3];
    const float* in_b     = (const float*)d_in[4];
    const float* out_w    = (const float*)d_in[5];
    const float* out_b    = (const float*)d_in[6];
    const float* ff1_w    = (const float*)d_in[7];
    const float* ff1_b    = (const float*)d_in[8];
    const float* ff2_w    = (const float*)d_in[9];
    const float* ff2_b    = (const float*)d_in[10];
    const float* ln1_w    = (const float*)d_in[11];
    const float* ln1_b    = (const float*)d_in[12];
    const float* ln2_w    = (const float*)d_in[13];
    const float* ln2_b    = (const float*)d_in[14];
    const float* mlp_w1   = (const float*)d_in[15];
    const float* mlp_b1   = (const float*)d_in[16];
    const float* mlp_w2   = (const float*)d_in[17];
    const float* mlp_b2   = (const float*)d_in[18];
    const float* mlp_w3   = (const float*)d_in[19];
    const float* mlp_b3   = (const float*)d_in[20];
    const float* highlights = (const float*)d_in[21];
    const float* negatives  = (const float*)d_in[22];
    float* out = (float*)d_out;

    float *feat0, *feat, *buf1, *buf2;
    __nv_bfloat16 *wbf, *qkvb, *xb, *ab1, *ab2, *ab3;
    cudaGetSymbolAddress((void**)&feat0, g_feat0);
    cudaGetSymbolAddress((void**)&feat,  g_feat);
    cudaGetSymbolAddress((void**)&buf1,  g_buf1);
    cudaGetSymbolAddress((void**)&buf2,  g_buf2);
    cudaGetSymbolAddress((void**)&qkvb,  g_qkvb);
    cudaGetSymbolAddress((void**)&xb,    g_xb);
    cudaGetSymbolAddress((void**)&ab1,   g_ab1);
    cudaGetSymbolAddress((void**)&ab2,   g_ab2);
    cudaGetSymbolAddress((void**)&ab3,   g_ab3);
    cudaGetSymbolAddress((void**)&wbf,   g_wbf);

    cudaFuncSetAttribute(attn_fused, cudaFuncAttributeMaxDynamicSharedMemorySize, ATTN_SMEM);
    cudaFuncSetAttribute(attn_fused, cudaFuncAttributePreferredSharedMemoryCarveout, 100);
    const int SM64  = 3 * (128 + 64) * 144;   // 82944
    const int SM192 = 3 * (128 + 192) * 144;  // 138240
    cudaFuncSetAttribute(gemm_bf16<64, 0, 0>,  cudaFuncAttributeMaxDynamicSharedMemorySize, SM64);
    cudaFuncSetAttribute(gemm_bf16<192, 0, 1>, cudaFuncAttributeMaxDynamicSharedMemorySize, SM192);
    cudaFuncSetAttribute(gemm_bf16<64, 2, 0>,  cudaFuncAttributeMaxDynamicSharedMemorySize, SM64);
    cudaFuncSetAttribute(gemm_bf16<64, 1, 2>,  cudaFuncAttributeMaxDynamicSharedMemorySize, SM64);
    cudaFuncSetAttribute(gemm_bf16<64, 0, 0>,  cudaFuncAttributePreferredSharedMemoryCarveout, 100);
    cudaFuncSetAttribute(gemm_bf16<192, 0, 1>, cudaFuncAttributePreferredSharedMemoryCarveout, 100);
    cudaFuncSetAttribute(gemm_bf16<64, 2, 0>,  cudaFuncAttributePreferredSharedMemoryCarveout, 100);
    cudaFuncSetAttribute(gemm_bf16<64, 1, 2>,  cudaFuncAttributePreferredSharedMemoryCarveout, 100);

    // ---- convert all weights + x to bf16 in one launch ----
    Cvt9 cv;
    const float* srcs[9] = {reduce_w, in_w, out_w, ff1_w, ff2_w, mlp_w1, mlp_w2, mlp_w3, x};
    __nv_bfloat16* dsts[9] = {wbf + OFF_RED, wbf + OFF_IN, wbf + OFF_OUT, wbf + OFF_FF1,
                              wbf + OFF_FF2, wbf + OFF_M1, wbf + OFF_M2, wbf + OFF_M3, xb};
    const int n4s[9] = {D_ * DIN_ / 4, L_ * 3 * D_ * D_ / 4, L_ * D_ * D_ / 4,
                        L_ * D_ * D_ / 4, L_ * D_ * D_ / 4, D_ * D_ / 4, D_ * D_ / 4,
                        Q_ * D_ / 4, B_ * DIN_ / 4};
    cv.cum[0] = 0;
    for (int i = 0; i < 9; i++) {
        cv.s[i] = srcs[i];
        cv.d[i] = dsts[i];
        cv.cum[i + 1] = cv.cum[i] + n4s[i];
    }
    cvt_bf16_all<<<(cv.cum[9] + 255) / 256, 256>>>(cv);

    // feat0 = inorm(x @ reduce_w^T + b)
    gemm_bf16<64, 0, 0><<<dim3(D_ / 64, B_ / 128), 256, SM64>>>(
        xb, wbf + OFF_RED, reduce_b, nullptr, buf1, DIN_, D_);
    rownorm_w<D_, false, false><<<B_ / 4, 128>>>(buf1, nullptr, nullptr, nullptr, feat0, ab1);

    const float* featPrev = feat0;
    for (int l = 0; l < L_; l++) {
        gemm_bf16<192, 0, 1><<<dim3(3 * D_ / 192, B_ / 128), 256, SM192>>>(
            ab1, wbf + OFF_IN + (size_t)l * 3 * D_ * D_, in_b + l * 3 * D_, nullptr,
            qkvb, D_, 3 * D_);
        attn_fused<<<dim3(B_ / 64, H_), 128, ATTN_SMEM>>>(qkvb, ab3);
        gemm_bf16<64, 2, 0><<<dim3(D_ / 64, B_ / 128), 256, SM64>>>(
            ab3, wbf + OFF_OUT + (size_t)l * D_ * D_, out_b + l * D_, featPrev, buf1, D_, D_);
        rownorm_w<D_, true, false><<<B_ / 4, 128>>>(buf1, nullptr, ln1_w + l * D_,
                                                    ln1_b + l * D_, feat, ab1);
        gemm_bf16<64, 1, 2><<<dim3(D_ / 64, B_ / 128), 256, SM64>>>(
            ab1, wbf + OFF_FF1 + (size_t)l * D_ * D_, ff1_b + l * D_, nullptr, ab2, D_, D_);
        gemm_bf16<64, 2, 0><<<dim3(D_ / 64, B_ / 128), 256, SM64>>>(
            ab2, wbf + OFF_FF2 + (size_t)l * D_ * D_, ff2_b + l * D_, feat, buf1, D_, D_);
        rownorm_w<D_, true, false><<<B_ / 4, 128>>>(buf1, nullptr, ln2_w + l * D_,
                                                    ln2_b + l * D_, feat, ab1);
        featPrev = feat;
    }

    rownorm_w<D_, false, true><<<B_ / 4, 128>>>(feat, feat0, nullptr, nullptr, nullptr, ab1);

    gemm_bf16<64, 1, 2><<<dim3(D_ / 64, B_ / 128), 256, SM64>>>(
        ab1, wbf + OFF_M1, mlp_b1, nullptr, ab2, D_, D_);
    gemm_bf16<64, 1, 2><<<dim3(D_ / 64, B_ / 128), 256, SM64>>>(
        ab2, wbf + OFF_M2, mlp_b2, nullptr, ab3, D_, D_);
    gemm_bf16<64, 0, 0><<<dim3(Q_ / 64, B_ / 128), 256, SM64>>>(
        ab3, wbf + OFF_M3, mlp_b3, nullptr, buf2, D_, Q_);

    cdist_logits<<<B_, 128>>>(buf2, highlights, negatives, out);
}

// round 16
// speedup vs baseline: 1.2963x; 1.1212x over previous
#include <cuda_runtime.h>
#include <cuda_bf16.h>
#include <math.h>

#define B_   2048
#define DIN_ 768
#define D_   512
#define H_   8
#define HD_  64
#define L_   3
#define P_   40
#define Q_   128
#define EPSF 1e-5f

// ---------------- scratch (device globals; no allocation allowed) ----------------
__device__ float g_feat0[B_ * D_];
__device__ float g_feat [B_ * D_];
__device__ float g_buf1 [B_ * D_];
__device__ float g_buf2 [B_ * D_];
__device__ __nv_bfloat16 g_qkvb[B_ * 3 * D_];   // bf16 qkv (q pre-scaled by 1/8)
__device__ __nv_bfloat16 g_xb  [B_ * DIN_];     // bf16 copy of x
__device__ __nv_bfloat16 g_ab1 [B_ * D_];
__device__ __nv_bfloat16 g_ab2 [B_ * D_];
__device__ __nv_bfloat16 g_ab3 [B_ * D_];
__device__ __nv_bfloat16 g_wbf[5800000];         // bf16 weight pool

#define OFF_RED  0
#define OFF_IN   (OFF_RED + D_ * DIN_)
#define OFF_OUT  (OFF_IN + L_ * 3 * D_ * D_)
#define OFF_FF1  (OFF_OUT + L_ * D_ * D_)
#define OFF_FF2  (OFF_FF1 + L_ * D_ * D_)
#define OFF_M1   (OFF_FF2 + L_ * D_ * D_)
#define OFF_M2   (OFF_M1 + D_ * D_)
#define OFF_M3   (OFF_M2 + D_ * D_)

// ---------------- helpers ----------------
__device__ __forceinline__ void mma_bf16(float* c, unsigned a0, unsigned a1,
                                         unsigned a2, unsigned a3,
                                         unsigned b0, unsigned b1) {
    asm volatile(
        "mma.sync.aligned.m16n8k16.row.col.f32.bf16.bf16.f32 "
        "{%0,%1,%2,%3}, {%4,%5,%6,%7}, {%8,%9}, {%0,%1,%2,%3};"
        : "+f"(c[0]), "+f"(c[1]), "+f"(c[2]), "+f"(c[3])
        : "r"(a0), "r"(a1), "r"(a2), "r"(a3), "r"(b0), "r"(b1));
}
__device__ __forceinline__ unsigned pack_bf16(float lo, float hi) {
    unsigned r; asm("cvt.rn.bf16x2.f32 %0, %1, %2;" : "=r"(r) : "f"(hi), "f"(lo));
    return r;
}
__device__ __forceinline__ void ldsm_x4(unsigned& a, unsigned& b, unsigned& c,
                                        unsigned& d, unsigned p) {
    asm volatile("ldmatrix.sync.aligned.m8n8.x4.shared.b16 {%0,%1,%2,%3}, [%4];"
                 : "=r"(a), "=r"(b), "=r"(c), "=r"(d) : "r"(p));
}
__device__ __forceinline__ void ldsm_x4t(unsigned& a, unsigned& b, unsigned& c,
                                         unsigned& d, unsigned p) {
    asm volatile("ldmatrix.sync.aligned.m8n8.x4.trans.shared.b16 {%0,%1,%2,%3}, [%4];"
                 : "=r"(a), "=r"(b), "=r"(c), "=r"(d) : "r"(p));
}
__device__ __forceinline__ void cp16(unsigned dst, const void* src) {
    asm volatile("cp.async.cg.shared.global [%0], [%1], 16;" :: "r"(dst), "l"(src));
}

// ---------------- merged fp32 -> bf16 conversion (9 segments, 1 launch) ----------------
struct Cvt9 {
    const float* s[9];
    __nv_bfloat16* d[9];
    int cum[10];
};
__global__ __launch_bounds__(256)
void cvt_bf16_all(Cvt9 a)
{
    int gid = blockIdx.x * 256 + threadIdx.x;
    if (gid >= a.cum[9]) return;
    int seg = 0;
    #pragma unroll
    for (int i = 1; i < 9; i++) if (gid >= a.cum[i]) seg = i;
    int idx = gid - a.cum[seg];
    float4 v = ((const float4*)a.s[seg])[idx];
    uint2 r;
    r.x = pack_bf16(v.x, v.y);
    r.y = pack_bf16(v.z, v.w);
    ((uint2*)a.d[seg])[idx] = r;
}

// ============ bf16 MMA GEMM: BK=64 (R15 proven), 3-stage cp.async ============
template<int BN, int EPI, int OUT>
__global__ __launch_bounds__(256, (BN > 128) ? 1 : 2)
void gemm_bf16(const __nv_bfloat16* __restrict__ A, const __nv_bfloat16* __restrict__ W,
               const float* __restrict__ bias, const float* __restrict__ res,
               void* __restrict__ Cv, int K, int ldc)
{
    constexpr int NT = BN / 16;
    constexpr int TROWS = 128 + BN;
    constexpr unsigned SSZ = TROWS * 144;
    constexpr int NCH = TROWS * 8 / 256;
    extern __shared__ unsigned char smx[];
    const unsigned smb = (unsigned)__cvta_generic_to_shared(smx);

    const int tid = threadIdx.x;
    const int w = tid >> 5, ln = tid & 31;
    const int g = ln >> 2, t = ln & 3;
    const int wm = (w >> 1) * 32, wn = (w & 1) * (BN / 2);
    const int m0 = blockIdx.y * 128, n0 = blockIdx.x * BN;

    const char* srcs[NCH];
    unsigned dsts[NCH];
    #pragma unroll
    for (int i = 0; i < NCH; i++) {
        const int c = tid + 256 * i;
        const int row = c >> 3, off = (c & 7) * 16;
        srcs[i] = (const char*)((row < 128)
                    ? (A + (size_t)(m0 + row) * K)
                    : (W + (size_t)(n0 + row - 128) * K)) + off;
        dsts[i] = (unsigned)(row * 144 + off);
    }

    const unsigned aOff = ((ln & 7) + ((ln >> 3) & 1) * 8) * 144 + (ln >> 4) * 16;
    const unsigned wOff = 128 * 144 + ((ln & 7) + ((ln >> 4) << 3)) * 144
                        + ((ln >> 3) & 1) * 16;

    float acc[2][NT][4];
    #pragma unroll
    for (int mt = 0; mt < 2; mt++)
        #pragma unroll
        for (int nt = 0; nt < NT; nt++)
            #pragma unroll
            for (int i = 0; i < 4; i++) acc[mt][nt][i] = 0.f;

    const int NKT = K >> 6;

    #define GISSUE(kt, slot) do {                                           \
        const unsigned bs = smb + (unsigned)(slot) * SSZ;                   \
        _Pragma("unroll")                                                   \
        for (int i_ = 0; i_ < NCH; i_++)                                    \
            cp16(bs + dsts[i_], srcs[i_] + (size_t)(kt) * 128);             \
        asm volatile("cp.async.commit_group;");                             \
    } while (0)

    GISSUE(0, 0);
    GISSUE(1, 1);

    int slot = 0;
    for (int kt = 0; kt < NKT; kt++) {
        if (kt + 1 < NKT) asm volatile("cp.async.wait_group 1;");
        else              asm volatile("cp.async.wait_group 0;");
        __syncthreads();
        if (kt + 2 < NKT) {
            int s2 = slot + 2; if (s2 >= 3) s2 -= 3;
            GISSUE(kt + 2, s2);
        }
        const unsigned base = smb + (unsigned)slot * SSZ;
        slot = (slot == 2) ? 0 : slot + 1;

        #pragma unroll
        for (int kg = 0; kg < 4; kg++) {
            unsigned a[2][4];
            ldsm_x4(a[0][0], a[0][1], a[0][2], a[0][3],
                    base + (wm)      * 144 + aOff + kg * 32);
            ldsm_x4(a[1][0], a[1][1], a[1][2], a[1][3],
                    base + (wm + 16) * 144 + aOff + kg * 32);
            #pragma unroll
            for (int ng = 0; ng < NT / 2; ng++) {
                unsigned b0, b1, b2, b3;
                ldsm_x4(b0, b1, b2, b3, base + wOff + (wn + 16 * ng) * 144 + kg * 32);
                mma_bf16(acc[0][2 * ng],     a[0][0], a[0][1], a[0][2], a[0][3], b0, b1);
                mma_bf16(acc[0][2 * ng + 1], a[0][0], a[0][1], a[0][2], a[0][3], b2, b3);
                mma_bf16(acc[1][2 * ng],     a[1][0], a[1][1], a[1][2], a[1][3], b0, b1);
                mma_bf16(acc[1][2 * ng + 1], a[1][0], a[1][1], a[1][2], a[1][3], b2, b3);
            }
        }
    }
    #undef GISSUE

    #pragma unroll
    for (int mt = 0; mt < 2; mt++) {
        const int r0 = m0 + wm + 16 * mt + g;
        #pragma unroll
        for (int nt = 0; nt < NT; nt++) {
            const int n = n0 + wn + 8 * nt + 2 * t;
            #pragma unroll
            for (int half = 0; half < 2; half++) {
                const size_t ro = (size_t)(r0 + 8 * half) * ldc;
                float2 v = { acc[mt][nt][2 * half], acc[mt][nt][2 * half + 1] };
                if (bias) { v.x += bias[n]; v.y += bias[n + 1]; }
                if (EPI == 1) { v.x = fmaxf(v.x, 0.f); v.y = fmaxf(v.y, 0.f); }
                if (EPI == 2) { v.x += res[ro + n]; v.y += res[ro + n + 1]; }
                if (OUT == 0) {
                    *(float2*)&((float*)Cv)[ro + n] = v;
                } else if (OUT == 1) {
                    const float sc = (n < 512) ? 0.125f : 1.0f;
                    *(unsigned*)&((__nv_bfloat16*)Cv)[ro + n] = pack_bf16(v.x * sc, v.y * sc);
                } else {
                    *(unsigned*)&((__nv_bfloat16*)Cv)[ro + n] = pack_bf16(v.x, v.y);
                }
            }
        }
    }
}

// ====== fused flash attention v3: 128 q-rows/CTA, 256 thr, 64-key softmax steps ======
#define KVROW 144
#define STG   (128 * KVROW)
#define ATTN_SMEM (4 * STG)

__global__ __launch_bounds__(256)
void attn_fused(const __nv_bfloat16* __restrict__ qkvb, __nv_bfloat16* __restrict__ ctxb)
{
    extern __shared__ unsigned char sm[];
    const unsigned smb = (unsigned)__cvta_generic_to_shared(sm);
    const int tid = threadIdx.x;
    const int w = tid >> 5, ln = tid & 31, g = ln >> 2, t = ln & 3;
    const int h = blockIdx.y;
    const int q0 = blockIdx.x * 128;
    const char* qb = (const char*)qkvb;

    // ---- stage Q (rows 0..127, scaled at qkv GEMM) into stage-0 K region ----
    {
        const int r = tid >> 1;
        const char* src = qb + (size_t)(q0 + r) * 3072 + h * 128 + (tid & 1) * 64;
        unsigned dst = smb + r * KVROW + (tid & 1) * 64;
        cp16(dst, src); cp16(dst + 16, src + 16);
        cp16(dst + 32, src + 32); cp16(dst + 48, src + 48);
    }
    asm volatile("cp.async.commit_group;");
    asm volatile("cp.async.wait_group 0;");
    __syncthreads();
    unsigned qa[4][4];
    {
        const unsigned qaddr = smb + (16 * w + (ln & 7) + ((ln >> 3) & 1) * 8) * KVROW
                             + (ln >> 4) * 16;
        #pragma unroll
        for (int kg = 0; kg < 4; kg++)
            ldsm_x4(qa[kg][0], qa[kg][1], qa[kg][2], qa[kg][3], qaddr + kg * 32);
    }
    __syncthreads();

    const unsigned koff = ((ln & 7) + ((ln >> 4) << 3)) * KVROW + ((ln >> 3) & 1) * 16;
    const unsigned voff = ((ln & 7) + ((ln >> 3) & 1) * 8) * KVROW + (ln >> 4) * 16;

    // stage K+V tile: 2 threads/row, 64B halves, 4 cp16 each
    #define ISSUE(ktg, buf) do {                                                   \
        const int r_ = tid >> 1;                                                   \
        const int hf_ = (tid & 1) * 64;                                            \
        unsigned kd = smb + (buf) * (2 * STG) + r_ * KVROW + hf_;                  \
        const char* ks = qb + (size_t)((ktg) * 128 + r_) * 3072 + 1024 + h * 128 + hf_; \
        _Pragma("unroll")                                                          \
        for (int c = 0; c < 4; c++) {                                              \
            cp16(kd + c * 16, ks + c * 16);                                        \
            cp16(kd + STG + c * 16, ks + 1024 + c * 16);                           \
        }                                                                          \
        asm volatile("cp.async.commit_group;");                                    \
    } while (0)

    float m0r = -1e30f, m1r = -1e30f, l0r = 0.f, l1r = 0.f;
    float o[8][4];
    #pragma unroll
    for (int nt = 0; nt < 8; nt++)
        #pragma unroll
        for (int i = 0; i < 4; i++) o[nt][i] = 0.f;

    ISSUE(0, 0);

    for (int kt = 0; kt < 16; kt++) {
        const int buf = kt & 1;
        asm volatile("cp.async.wait_group 0;");
        __syncthreads();
        if (kt < 15) ISSUE(kt + 1, buf ^ 1);
        const unsigned Kb = smb + buf * (2 * STG) + koff;
        const unsigned Vb = smb + buf * (2 * STG) + STG + voff;

        #pragma unroll
        for (int hk = 0; hk < 2; hk++) {
            const unsigned rowb = (unsigned)(64 * hk) * KVROW;

            // ---- S = Q @ K^T over 64 keys ----
            float s[8][4];
            #pragma unroll
            for (int nt = 0; nt < 8; nt++)
                #pragma unroll
                for (int i = 0; i < 4; i++) s[nt][i] = 0.f;
            #pragma unroll
            for (int j = 0; j < 4; j++) {
                #pragma unroll
                for (int kg = 0; kg < 4; kg++) {
                    unsigned b0, b1, b2, b3;
                    ldsm_x4(b0, b1, b2, b3, Kb + rowb + j * (16 * KVROW) + kg * 32);
                    mma_bf16(s[2 * j],     qa[kg][0], qa[kg][1], qa[kg][2], qa[kg][3], b0, b1);
                    mma_bf16(s[2 * j + 1], qa[kg][0], qa[kg][1], qa[kg][2], qa[kg][3], b2, b3);
                }
            }

            // ---- online softmax (64 keys) ----
            float mx0 = -1e30f, mx1 = -1e30f;
            #pragma unroll
            for (int nt = 0; nt < 8; nt++) {
                mx0 = fmaxf(mx0, fmaxf(s[nt][0], s[nt][1]));
                mx1 = fmaxf(mx1, fmaxf(s[nt][2], s[nt][3]));
            }
            mx0 = fmaxf(mx0, __shfl_xor_sync(0xffffffffu, mx0, 1));
            mx0 = fmaxf(mx0, __shfl_xor_sync(0xffffffffu, mx0, 2));
            mx1 = fmaxf(mx1, __shfl_xor_sync(0xffffffffu, mx1, 1));
            mx1 = fmaxf(mx1, __shfl_xor_sync(0xffffffffu, mx1, 2));
            const float mn0 = fmaxf(m0r, mx0), mn1 = fmaxf(m1r, mx1);
            const float al0 = __expf(m0r - mn0), al1 = __expf(m1r - mn1);
            m0r = mn0; m1r = mn1;
            float sum0 = 0.f, sum1 = 0.f;
            #pragma unroll
            for (int nt = 0; nt < 8; nt++) {
                s[nt][0] = __expf(s[nt][0] - mn0);
                s[nt][1] = __expf(s[nt][1] - mn0);
                s[nt][2] = __expf(s[nt][2] - mn1);
                s[nt][3] = __expf(s[nt][3] - mn1);
                sum0 += s[nt][0] + s[nt][1];
                sum1 += s[nt][2] + s[nt][3];
            }
            sum0 += __shfl_xor_sync(0xffffffffu, sum0, 1);
            sum0 += __shfl_xor_sync(0xffffffffu, sum0, 2);
            sum1 += __shfl_xor_sync(0xffffffffu, sum1, 1);
            sum1 += __shfl_xor_sync(0xffffffffu, sum1, 2);
            l0r = l0r * al0 + sum0;
            l1r = l1r * al1 + sum1;
            #pragma unroll
            for (int nt = 0; nt < 8; nt++) {
                o[nt][0] *= al0; o[nt][1] *= al0;
                o[nt][2] *= al1; o[nt][3] *= al1;
            }

            // ---- pack P, O += P @ V over these 64 keys ----
            unsigned pa[4][4];
            #pragma unroll
            for (int kg = 0; kg < 4; kg++) {
                pa[kg][0] = pack_bf16(s[2 * kg][0],     s[2 * kg][1]);
                pa[kg][1] = pack_bf16(s[2 * kg][2],     s[2 * kg][3]);
                pa[kg][2] = pack_bf16(s[2 * kg + 1][0], s[2 * kg + 1][1]);
                pa[kg][3] = pack_bf16(s[2 * kg + 1][2], s[2 * kg + 1][3]);
            }
            #pragma unroll
            for (int i = 0; i < 4; i++) {
                #pragma unroll
                for (int jj = 0; jj < 4; jj++) {
                    unsigned b0, b1, b2, b3;
                    ldsm_x4t(b0, b1, b2, b3, Vb + rowb + i * (16 * KVROW) + jj * 32);
                    mma_bf16(o[2 * jj],     pa[i][0], pa[i][1], pa[i][2], pa[i][3], b0, b1);
                    mma_bf16(o[2 * jj + 1], pa[i][0], pa[i][1], pa[i][2], pa[i][3], b2, b3);
                }
            }
        }
    }
    #undef ISSUE

    const float inv0 = 1.0f / l0r, inv1 = 1.0f / l1r;
    #pragma unroll
    for (int nt = 0; nt < 8; nt++) {
        const int n = h * 64 + 8 * nt + 2 * t;
        const size_t r0 = (size_t)(q0 + 16 * w + g) * D_;
        const size_t r1 = (size_t)(q0 + 16 * w + g + 8) * D_;
        *(unsigned*)&ctxb[r0 + n] = pack_bf16(o[nt][0] * inv0, o[nt][1] * inv0);
        *(unsigned*)&ctxb[r1 + n] = pack_bf16(o[nt][2] * inv1, o[nt][3] * inv1);
    }
}

// ---------------- warp-per-row normalize (no barriers, no smem) ----------------
template<int N, bool AFFINE, bool ADD>
__global__ __launch_bounds__(128)
void rownorm_w(const float* __restrict__ src, const float* __restrict__ addv,
               const float* __restrict__ w, const float* __restrict__ bb,
               float* __restrict__ dst, __nv_bfloat16* __restrict__ dstb)
{
    constexpr int NV = N / 128;
    const int ln = threadIdx.x & 31;
    const int row = blockIdx.x * 4 + (threadIdx.x >> 5);
    const size_t base = (size_t)row * N;

    float4 v[NV];
    float s = 0.f;
    #pragma unroll
    for (int i = 0; i < NV; i++) {
        v[i] = *(const float4*)&src[base + i * 128 + ln * 4];
        s += v[i].x + v[i].y + v[i].z + v[i].w;
    }
    #pragma unroll
    for (int o = 16; o > 0; o >>= 1) s += __shfl_xor_sync(0xffffffffu, s, o);
    const float mean = s * (1.0f / N);
    float q = 0.f;
    #pragma unroll
    for (int i = 0; i < NV; i++) {
        float d0 = v[i].x - mean, d1 = v[i].y - mean;
        float d2 = v[i].z - mean, d3 = v[i].w - mean;
        q += d0 * d0 + d1 * d1 + d2 * d2 + d3 * d3;
    }
    #pragma unroll
    for (int o = 16; o > 0; o >>= 1) q += __shfl_xor_sync(0xffffffffu, q, o);
    const float r = rsqrtf(q * (1.0f / N) + EPSF);

    #pragma unroll
    for (int i = 0; i < NV; i++) {
        const int c = i * 128 + ln * 4;
        float y0 = (v[i].x - mean) * r, y1 = (v[i].y - mean) * r;
        float y2 = (v[i].z - mean) * r, y3 = (v[i].w - mean) * r;
        if (AFFINE) {
            float4 ww = *(const float4*)&w[c];
            float4 bv = *(const float4*)&bb[c];
            y0 = y0 * ww.x + bv.x; y1 = y1 * ww.y + bv.y;
            y2 = y2 * ww.z + bv.z; y3 = y3 * ww.w + bv.w;
        }
        if (ADD) {
            float4 av = *(const float4*)&addv[base + c];
            y0 += av.x; y1 += av.y; y2 += av.z; y3 += av.w;
        }
        if (dst) {
            float4 ov = {y0, y1, y2, y3};
            *(float4*)&dst[base + c] = ov;
        }
        if (dstb) {
            uint2 ob;
            ob.x = pack_bf16(y0, y1);
            ob.y = pack_bf16(y2, y3);
            *(uint2*)&dstb[base + c] = ob;
        }
    }
}

// ---------------- fused InstanceNorm + cdist + logits ----------------
__global__ __launch_bounds__(128)
void cdist_logits(const float* __restrict__ zraw, const float* __restrict__ hi,
                  const float* __restrict__ neg, float* __restrict__ out)
{
    __shared__ float zr[Q_];
    __shared__ float red[8];
    const int b = blockIdx.x, t = threadIdx.x;
    const int ln = t & 31, wv = t >> 5;

    float v = zraw[(size_t)b * Q_ + t];
    float s = v, s2 = v * v;
    #pragma unroll
    for (int o = 16; o > 0; o >>= 1) {
        s  += __shfl_xor_sync(0xffffffffu, s,  o);
        s2 += __shfl_xor_sync(0xffffffffu, s2, o);
    }
    if (ln == 0) { red[wv] = s; red[4 + wv] = s2; }
    __syncthreads();
    s  = red[0] + red[1] + red[2] + red[3];
    s2 = red[4] + red[5] + red[6] + red[7];
    const float mean = s * (1.0f / Q_);
    const float var  = s2 * (1.0f / Q_) - mean * mean;
    const float rs = rsqrtf(var + EPSF);
    zr[t] = (v - mean) * rs;
    __syncthreads();

    const int slot = (wv & 1) * 32 + ln;
    const float* pb = (wv < 2) ? hi : neg;
    float d = 3.4e38f;
    if (slot < P_) {
        const float* p = pb + (size_t)slot * Q_;
        float acc = 0.f;
        #pragma unroll 8
        for (int k = 0; k < Q_; k++) { float df = zr[k] - p[k]; acc = fmaf(df, df, acc); }
        d = sqrtf(acc);
    }
    #pragma unroll
    for (int o = 16; o > 0; o >>= 1) d = fminf(d, __shfl_xor_sync(0xffffffffu, d, o));
    if (ln == 0) red[wv] = d;
    __syncthreads();
    if (t == 0) out[b * 2 + 1] = -fminf(red[0], red[1]);
    if (t == 64) out[b * 2 + 0] = -fminf(red[2], red[3]);
}

// ---------------- host driver ----------------
extern "C" void kernel_launch(void* const* d_in, const int* in_sizes, int n_in,
                              void* d_out, int out_size)
{
    const float* x        = (const float*)d_in[0];
    const float* reduce_w = (const float*)d_in[1];
    const float* reduce_b = (const float*)d_in[2];
    const float* in_w     = (const float*)d_in[3];
    const float* in_b     = (const float*)d_in[4];
    const float* out_w    = (const float*)d_in[5];
    const float* out_b    = (const float*)d_in[6];
    const float* ff1_w    = (const float*)d_in[7];
    const float* ff1_b    = (const float*)d_in[8];
    const float* ff2_w    = (const float*)d_in[9];
    const float* ff2_b    = (const float*)d_in[10];
    const float* ln1_w    = (const float*)d_in[11];
    const float* ln1_b    = (const float*)d_in[12];
    const float* ln2_w    = (const float*)d_in[13];
    const float* ln2_b    = (const float*)d_in[14];
    const float* mlp_w1   = (const float*)d_in[15];
    const float* mlp_b1   = (const float*)d_in[16];
    const float* mlp_w2   = (const float*)d_in[17];
    const float* mlp_b2   = (const float*)d_in[18];
    const float* mlp_w3   = (const float*)d_in[19];
    const float* mlp_b3   = (const float*)d_in[20];
    const float* highlights = (const float*)d_in[21];
    const float* negatives  = (const float*)d_in[22];
    float* out = (float*)d_out;

    float *feat0, *feat, *buf1, *buf2;
    __nv_bfloat16 *wbf, *qkvb, *xb, *ab1, *ab2, *ab3;
    cudaGetSymbolAddress((void**)&feat0, g_feat0);
    cudaGetSymbolAddress((void**)&feat,  g_feat);
    cudaGetSymbolAddress((void**)&buf1,  g_buf1);
    cudaGetSymbolAddress((void**)&buf2,  g_buf2);
    cudaGetSymbolAddress((void**)&qkvb,  g_qkvb);
    cudaGetSymbolAddress((void**)&xb,    g_xb);
    cudaGetSymbolAddress((void**)&ab1,   g_ab1);
    cudaGetSymbolAddress((void**)&ab2,   g_ab2);
    cudaGetSymbolAddress((void**)&ab3,   g_ab3);
    cudaGetSymbolAddress((void**)&wbf,   g_wbf);

    cudaFuncSetAttribute(attn_fused, cudaFuncAttributeMaxDynamicSharedMemorySize, ATTN_SMEM);
    cudaFuncSetAttribute(attn_fused, cudaFuncAttributePreferredSharedMemoryCarveout, 100);
    const int SM64  = 3 * (128 + 64) * 144;   // 82944
    const int SM192 = 3 * (128 + 192) * 144;  // 138240
    cudaFuncSetAttribute(gemm_bf16<64, 0, 0>,  cudaFuncAttributeMaxDynamicSharedMemorySize, SM64);
    cudaFuncSetAttribute(gemm_bf16<192, 0, 1>, cudaFuncAttributeMaxDynamicSharedMemorySize, SM192);
    cudaFuncSetAttribute(gemm_bf16<64, 2, 0>,  cudaFuncAttributeMaxDynamicSharedMemorySize, SM64);
    cudaFuncSetAttribute(gemm_bf16<64, 1, 2>,  cudaFuncAttributeMaxDynamicSharedMemorySize, SM64);
    cudaFuncSetAttribute(gemm_bf16<64, 0, 0>,  cudaFuncAttributePreferredSharedMemoryCarveout, 100);
    cudaFuncSetAttribute(gemm_bf16<192, 0, 1>, cudaFuncAttributePreferredSharedMemoryCarveout, 100);
    cudaFuncSetAttribute(gemm_bf16<64, 2, 0>,  cudaFuncAttributePreferredSharedMemoryCarveout, 100);
    cudaFuncSetAttribute(gemm_bf16<64, 1, 2>,  cudaFuncAttributePreferredSharedMemoryCarveout, 100);

    // ---- convert all weights + x to bf16 in one launch ----
    Cvt9 cv;
    const float* srcs[9] = {reduce_w, in_w, out_w, ff1_w, ff2_w, mlp_w1, mlp_w2, mlp_w3, x};
    __nv_bfloat16* dsts[9] = {wbf + OFF_RED, wbf + OFF_IN, wbf + OFF_OUT, wbf + OFF_FF1,
                              wbf + OFF_FF2, wbf + OFF_M1, wbf + OFF_M2, wbf + OFF_M3, xb};
    const int n4s[9] = {D_ * DIN_ / 4, L_ * 3 * D_ * D_ / 4, L_ * D_ * D_ / 4,
                        L_ * D_ * D_ / 4, L_ * D_ * D_ / 4, D_ * D_ / 4, D_ * D_ / 4,
                        Q_ * D_ / 4, B_ * DIN_ / 4};
    cv.cum[0] = 0;
    for (int i = 0; i < 9; i++) {
        cv.s[i] = srcs[i];
        cv.d[i] = dsts[i];
        cv.cum[i + 1] = cv.cum[i] + n4s[i];
    }
    cvt_bf16_all<<<(cv.cum[9] + 255) / 256, 256>>>(cv);

    // feat0 = inorm(x @ reduce_w^T + b)
    gemm_bf16<64, 0, 0><<<dim3(D_ / 64, B_ / 128), 256, SM64>>>(
        xb, wbf + OFF_RED, reduce_b, nullptr, buf1, DIN_, D_);
    rownorm_w<D_, false, false><<<B_ / 4, 128>>>(buf1, nullptr, nullptr, nullptr, feat0, ab1);

    const float* featPrev = feat0;
    for (int l = 0; l < L_; l++) {
        gemm_bf16<192, 0, 1><<<dim3(3 * D_ / 192, B_ / 128), 256, SM192>>>(
            ab1, wbf + OFF_IN + (size_t)l * 3 * D_ * D_, in_b + l * 3 * D_, nullptr,
            qkvb, D_, 3 * D_);
        attn_fused<<<dim3(B_ / 128, H_), 256, ATTN_SMEM>>>(qkvb, ab3);
        gemm_bf16<64, 2, 0><<<dim3(D_ / 64, B_ / 128), 256, SM64>>>(
            ab3, wbf + OFF_OUT + (size_t)l * D_ * D_, out_b + l * D_, featPrev, buf1, D_, D_);
        rownorm_w<D_, true, false><<<B_ / 4, 128>>>(buf1, nullptr, ln1_w + l * D_,
                                                    ln1_b + l * D_, feat, ab1);
        gemm_bf16<64, 1, 2><<<dim3(D_ / 64, B_ / 128), 256, SM64>>>(
            ab1, wbf + OFF_FF1 + (size_t)l * D_ * D_, ff1_b + l * D_, nullptr, ab2, D_, D_);
        gemm_bf16<64, 2, 0><<<dim3(D_ / 64, B_ / 128), 256, SM64>>>(
            ab2, wbf + OFF_FF2 + (size_t)l * D_ * D_, ff2_b + l * D_, feat, buf1, D_, D_);
        rownorm_w<D_, true, false><<<B_ / 4, 128>>>(buf1, nullptr, ln2_w + l * D_,
                                                    ln2_b + l * D_, feat, ab1);
        featPrev = feat;
    }

    rownorm_w<D_, false, true><<<B_ / 4, 128>>>(feat, feat0, nullptr, nullptr, nullptr, ab1);

    gemm_bf16<64, 1, 2><<<dim3(D_ / 64, B_ / 128), 256, SM64>>>(
        ab1, wbf + OFF_M1, mlp_b1, nullptr, ab2, D_, D_);
    gemm_bf16<64, 1, 2><<<dim3(D_ / 64, B_ / 128), 256, SM64>>>(
        ab2, wbf + OFF_M2, mlp_b2, nullptr, ab3, D_, D_);
    gemm_bf16<64, 0, 0><<<dim3(Q_ / 64, B_ / 128), 256, SM64>>>(
        ab3, wbf + OFF_M3, mlp_b3, nullptr, buf2, D_, Q_);

    cdist_logits<<<B_, 128>>>(buf2, highlights, negatives, out);
}